// round 1
// baseline (speedup 1.0000x reference)
#include <cuda_runtime.h>
#include <math.h>

// ---------------------------------------------------------------------------
// Problem constants (fixed by the dataset):
//   B=2 batch, N=2048 tokens, C=1024 model dim (P=Q=C), K=16 heads, D=64 head dim
// Pipeline:
//   Kp[b,k,m,d] = y'[b,m,:] . Lam_x[k,:,d]
//   Qp[b,k,n,d] = y'[b,n,:] . Lam_y[k,:,d]
//   Vp[b,k,m,d] = y'[b,m,:] . Th_x[k,:,d]
//   S[m,n] = (Kp[m].Qp[n] + mask[m,n]) / sqrt(D);  A = softmax over m
//   O[b,n,k,d] = sum_m A[m,n] Vp[m,d]
//   out[b,n,q] = sum_{k,d} O[b,n,k,d] * Th_y[k,q,d]
// ---------------------------------------------------------------------------

#define BB   2
#define NTOK 2048
#define CDIM 1024
#define KH   16
#define DH   64
#define KD   (KH*DH)          // 1024
#define INV_TEMP 0.125f       // 1/sqrt(64)

// Scratch (static __device__ arrays; no runtime allocation allowed)
__device__ float g_Kp[(size_t)BB*KH*NTOK*DH];   // 16 MB  [b][k][m][d]
__device__ float g_Qp[(size_t)BB*KH*NTOK*DH];   // 16 MB  [b][k][n][d]
__device__ float g_Vp[(size_t)BB*KH*NTOK*DH];   // 16 MB  [b][k][m][d]
__device__ float g_Ob[(size_t)BB*NTOK*KD];      // 16 MB  [b][n][k*64+d]
__device__ float g_Wt[(size_t)KD*CDIM];         //  4 MB  [k*64+d][q]

// ---------------------------------------------------------------------------
// Kernel 1: fused triple projection.  Block = (64 m-rows) x (192 cols = 3x64 d)
// for one (b,k).  256 threads; microtile 8 rows x 6 cols (cols = tx + 32*j).
// ---------------------------------------------------------------------------
__global__ __launch_bounds__(256) void proj_kernel(
    const float* __restrict__ y, const float* __restrict__ Lx,
    const float* __restrict__ Ly, const float* __restrict__ Tx)
{
    __shared__ float As[64][17];    // [m_local][kk]
    __shared__ float Bs[16][192];   // [kk][w*64+d]

    const int m0 = blockIdx.x * 64;
    const int k  = blockIdx.y;
    const int b  = blockIdx.z;
    const int t  = threadIdx.x;
    const int tx = t & 31;
    const int ty = t >> 5;

    float acc[8][6];
#pragma unroll
    for (int i = 0; i < 8; i++)
#pragma unroll
        for (int j = 0; j < 6; j++) acc[i][j] = 0.0f;

    const float* Aptr = y + (size_t)(b*NTOK + m0)*CDIM;
    const int ar  = t >> 2;
    const int ac4 = (t & 3) * 4;

    for (int kc = 0; kc < CDIM; kc += 16) {
        // Load A tile 64x16
        float4 av = *(const float4*)(Aptr + (size_t)ar*CDIM + kc + ac4);
        As[ar][ac4+0] = av.x; As[ar][ac4+1] = av.y;
        As[ar][ac4+2] = av.z; As[ar][ac4+3] = av.w;
        // Load B tile 16x192 (3 weight matrices, d contiguous)
#pragma unroll
        for (int s = 0; s < 3; s++) {
            int f   = t + 256*s;        // 0..767 float4 tiles
            int c   = f / 48;
            int rem = f - c*48;
            int w   = rem >> 4;
            int d4  = (rem & 15) * 4;
            const float* Wp = (w == 0) ? Lx : ((w == 1) ? Ly : Tx);
            float4 bv = *(const float4*)(Wp + ((size_t)(k*CDIM + kc + c))*DH + d4);
            *(float4*)&Bs[c][w*64 + d4] = bv;
        }
        __syncthreads();
#pragma unroll
        for (int kk = 0; kk < 16; kk++) {
            float a[8], bv[6];
#pragma unroll
            for (int i = 0; i < 8; i++) a[i] = As[ty*8 + i][kk];
#pragma unroll
            for (int j = 0; j < 6; j++) bv[j] = Bs[kk][tx + 32*j];
#pragma unroll
            for (int i = 0; i < 8; i++)
#pragma unroll
                for (int j = 0; j < 6; j++)
                    acc[i][j] = fmaf(a[i], bv[j], acc[i][j]);
        }
        __syncthreads();
    }

    const size_t base = ((size_t)((b*KH + k)*NTOK) + m0) * DH;
#pragma unroll
    for (int j = 0; j < 6; j++) {
        int c = tx + 32*j;
        int w = c >> 6;
        int d = c & 63;
        float* dst = (w == 0) ? g_Kp : ((w == 1) ? g_Qp : g_Vp);
#pragma unroll
        for (int i = 0; i < 8; i++)
            dst[base + (size_t)(ty*8 + i)*DH + d] = acc[i][j];
    }
}

// ---------------------------------------------------------------------------
// Kernel 2: flash attention per (b,k).  Block = 64 queries (n), loops over all
// m in tiles of 64.  256 threads as 16x16; 4x4 microtile.  Softmax row state
// (running max / sum) replicated in registers across each 16-lane row group.
// Dynamic smem: Qs[64][65] Ks[64][65] Vs[64][68] Ps[64][68]  (68096 B)
// ---------------------------------------------------------------------------
#define ATTN_SMEM_BYTES ((2*64*65 + 2*64*68) * 4)

__global__ __launch_bounds__(256) void attn_kernel(const float* __restrict__ mask)
{
    extern __shared__ float sm[];
    float* Qs = sm;                       // stride 65
    float* Ks = sm + 64*65;               // stride 65
    float* Vs = sm + 2*64*65;             // stride 68 (float4-aligned)
    float* Ps = sm + 2*64*65 + 64*68;     // stride 68 (float4-aligned)

    const int n0 = blockIdx.x * 64;
    const int k  = blockIdx.y;
    const int b  = blockIdx.z;
    const int t  = threadIdx.x;
    const int tx = t & 15;
    const int ty = t >> 4;

    const float* Qg = g_Qp + ((size_t)((b*KH + k)*NTOK) + n0)*DH;
    const float* Kg = g_Kp + (size_t)((b*KH + k)*NTOK)*DH;
    const float* Vg = g_Vp + (size_t)((b*KH + k)*NTOK)*DH;

    const int lr = t >> 2;          // 0..63 tile row for loads
    const int lcb = (t & 3) * 16;   // 16-float span per thread

    // Load Q tile once
#pragma unroll
    for (int u = 0; u < 4; u++) {
        int c4 = lcb + u*4;
        float4 v = *(const float4*)(Qg + (size_t)lr*DH + c4);
        Qs[lr*65 + c4+0] = v.x; Qs[lr*65 + c4+1] = v.y;
        Qs[lr*65 + c4+2] = v.z; Qs[lr*65 + c4+3] = v.w;
    }

    float Ot[4][4];
    float mprev[4], lsum[4];
#pragma unroll
    for (int i = 0; i < 4; i++) {
        mprev[i] = -1e30f; lsum[i] = 0.0f;
#pragma unroll
        for (int j = 0; j < 4; j++) Ot[i][j] = 0.0f;
    }

    for (int mt = 0; mt < NTOK/64; mt++) {
        __syncthreads();   // protects Ks/Vs/Ps from previous iteration readers
        const float* Kt = Kg + (size_t)mt*64*DH;
        const float* Vt = Vg + (size_t)mt*64*DH;
#pragma unroll
        for (int u = 0; u < 4; u++) {
            int c4 = lcb + u*4;
            float4 kv = *(const float4*)(Kt + (size_t)lr*DH + c4);
            Ks[lr*65 + c4+0] = kv.x; Ks[lr*65 + c4+1] = kv.y;
            Ks[lr*65 + c4+2] = kv.z; Ks[lr*65 + c4+3] = kv.w;
            float4 vv = *(const float4*)(Vt + (size_t)lr*DH + c4);
            *(float4*)&Vs[lr*68 + c4] = vv;
        }
        __syncthreads();

        // S tile: s[i][j] = Q[n0+ty*4+i] . K[mt*64+tx*4+j]
        float s[4][4];
#pragma unroll
        for (int i = 0; i < 4; i++)
#pragma unroll
            for (int j = 0; j < 4; j++) s[i][j] = 0.0f;
#pragma unroll 4
        for (int dd = 0; dd < 64; dd++) {
            float q[4], kk_[4];
#pragma unroll
            for (int i = 0; i < 4; i++) q[i]  = Qs[(ty*4 + i)*65 + dd];
#pragma unroll
            for (int j = 0; j < 4; j++) kk_[j] = Ks[(tx*4 + j)*65 + dd];
#pragma unroll
            for (int i = 0; i < 4; i++)
#pragma unroll
                for (int j = 0; j < 4; j++)
                    s[i][j] = fmaf(q[i], kk_[j], s[i][j]);
        }

        // mask (mask[m][n], n contiguous over i) + temperature
        const int mg = mt*64 + tx*4;
#pragma unroll
        for (int j = 0; j < 4; j++) {
            float4 mv = *(const float4*)(mask + (size_t)(mg + j)*NTOK + n0 + ty*4);
            s[0][j] = (s[0][j] + mv.x) * INV_TEMP;
            s[1][j] = (s[1][j] + mv.y) * INV_TEMP;
            s[2][j] = (s[2][j] + mv.z) * INV_TEMP;
            s[3][j] = (s[3][j] + mv.w) * INV_TEMP;
        }

        // Online softmax over m (reduce across the 16 lanes sharing a row group)
#pragma unroll
        for (int i = 0; i < 4; i++) {
            float rm = fmaxf(fmaxf(s[i][0], s[i][1]), fmaxf(s[i][2], s[i][3]));
            rm = fmaxf(rm, __shfl_xor_sync(0xffffffffu, rm, 1));
            rm = fmaxf(rm, __shfl_xor_sync(0xffffffffu, rm, 2));
            rm = fmaxf(rm, __shfl_xor_sync(0xffffffffu, rm, 4));
            rm = fmaxf(rm, __shfl_xor_sync(0xffffffffu, rm, 8));
            float mnew = fmaxf(mprev[i], rm);
            float corr = __expf(mprev[i] - mnew);
            lsum[i] *= corr;
#pragma unroll
            for (int j = 0; j < 4; j++) Ot[i][j] *= corr;
            float rs = 0.0f;
#pragma unroll
            for (int j = 0; j < 4; j++) {
                s[i][j] = __expf(s[i][j] - mnew);
                rs += s[i][j];
            }
            rs += __shfl_xor_sync(0xffffffffu, rs, 1);
            rs += __shfl_xor_sync(0xffffffffu, rs, 2);
            rs += __shfl_xor_sync(0xffffffffu, rs, 4);
            rs += __shfl_xor_sync(0xffffffffu, rs, 8);
            lsum[i] += rs;
            mprev[i] = mnew;
            *(float4*)&Ps[(ty*4 + i)*68 + tx*4] =
                make_float4(s[i][0], s[i][1], s[i][2], s[i][3]);
        }
        __syncthreads();

        // O += P @ V  (Ot cols j now index d = tx*4+j)
#pragma unroll 4
        for (int ml = 0; ml < 64; ml++) {
            float pv[4], vv[4];
#pragma unroll
            for (int i = 0; i < 4; i++) pv[i] = Ps[(ty*4 + i)*68 + ml];
#pragma unroll
            for (int j = 0; j < 4; j++) vv[j] = Vs[ml*68 + tx*4 + j];
#pragma unroll
            for (int i = 0; i < 4; i++)
#pragma unroll
                for (int j = 0; j < 4; j++)
                    Ot[i][j] = fmaf(pv[i], vv[j], Ot[i][j]);
        }
    }

    // Normalize + write O[b][n][k][d]
#pragma unroll
    for (int i = 0; i < 4; i++) {
        float inv = 1.0f / lsum[i];
        int n = n0 + ty*4 + i;
        float4 o = make_float4(Ot[i][0]*inv, Ot[i][1]*inv, Ot[i][2]*inv, Ot[i][3]*inv);
        *(float4*)(g_Ob + (((size_t)(b*NTOK + n))*KH + k)*DH + tx*4) = o;
    }
}

// ---------------------------------------------------------------------------
// Kernel 3: transpose Th_y [K][Q][D] -> g_Wt [k*64+d][q]
// ---------------------------------------------------------------------------
__global__ __launch_bounds__(256) void transpose_thy(const float* __restrict__ Ty)
{
    __shared__ float tile[32][33];
    const int q0 = blockIdx.x * 32;
    const int d0 = blockIdx.y * 32;
    const int k  = blockIdx.z;
    const int tx = threadIdx.x;     // 32
    const int ty = threadIdx.y;     // 8
#pragma unroll
    for (int s = 0; s < 4; s++) {
        int qq = ty + 8*s;
        tile[qq][tx] = Ty[((size_t)(k*CDIM + q0 + qq))*DH + d0 + tx];
    }
    __syncthreads();
#pragma unroll
    for (int s = 0; s < 4; s++) {
        int r = ty + 8*s;
        g_Wt[(size_t)(k*DH + d0 + r)*CDIM + q0 + tx] = tile[tx][r];
    }
}

// ---------------------------------------------------------------------------
// Kernel 4: output GEMM  out[bn][q] = g_Ob[bn][:] @ g_Wt[:][q]
// Block tile 64 x 128, 256 threads, microtile 8 rows x 4 cols (cols tx+32j).
// ---------------------------------------------------------------------------
__global__ __launch_bounds__(256) void outgemm_kernel(float* __restrict__ out)
{
    __shared__ float As[64][17];
    __shared__ float Bs[16][128];

    const int q0 = blockIdx.x * 128;
    const int m0 = blockIdx.y * 64;
    const int t  = threadIdx.x;
    const int tx = t & 31;
    const int ty = t >> 5;

    float acc[8][4];
#pragma unroll
    for (int i = 0; i < 8; i++)
#pragma unroll
        for (int j = 0; j < 4; j++) acc[i][j] = 0.0f;

    const int ar  = t >> 2;
    const int ac4 = (t & 3) * 4;

    for (int kc = 0; kc < KD; kc += 16) {
        float4 av = *(const float4*)(g_Ob + (size_t)(m0 + ar)*KD + kc + ac4);
        As[ar][ac4+0] = av.x; As[ar][ac4+1] = av.y;
        As[ar][ac4+2] = av.z; As[ar][ac4+3] = av.w;
#pragma unroll
        for (int s = 0; s < 2; s++) {
            int f  = t + 256*s;
            int c  = f >> 5;
            int q4 = (f & 31) * 4;
            *(float4*)&Bs[c][q4] =
                *(const float4*)(g_Wt + (size_t)(kc + c)*CDIM + q0 + q4);
        }
        __syncthreads();
#pragma unroll
        for (int kk = 0; kk < 16; kk++) {
            float a[8], bv[4];
#pragma unroll
            for (int i = 0; i < 8; i++) a[i] = As[ty*8 + i][kk];
#pragma unroll
            for (int j = 0; j < 4; j++) bv[j] = Bs[kk][tx + 32*j];
#pragma unroll
            for (int i = 0; i < 8; i++)
#pragma unroll
                for (int j = 0; j < 4; j++)
                    acc[i][j] = fmaf(a[i], bv[j], acc[i][j]);
        }
        __syncthreads();
    }
#pragma unroll
    for (int i = 0; i < 8; i++)
#pragma unroll
        for (int j = 0; j < 4; j++)
            out[(size_t)(m0 + ty*8 + i)*CDIM + q0 + tx + 32*j] = acc[i][j];
}

// ---------------------------------------------------------------------------
extern "C" void kernel_launch(void* const* d_in, const int* in_sizes, int n_in,
                              void* d_out, int out_size)
{
    (void)in_sizes; (void)n_in; (void)out_size;
    const float* y    = (const float*)d_in[0];
    const float* mask = (const float*)d_in[1];
    const float* Lx   = (const float*)d_in[2];
    const float* Ly   = (const float*)d_in[3];
    const float* Tx   = (const float*)d_in[4];
    const float* Ty   = (const float*)d_in[5];
    float* out = (float*)d_out;

    cudaFuncSetAttribute(attn_kernel,
        cudaFuncAttributeMaxDynamicSharedMemorySize, ATTN_SMEM_BYTES);

    proj_kernel<<<dim3(NTOK/64, KH, BB), 256>>>(y, Lx, Ly, Tx);
    transpose_thy<<<dim3(CDIM/32, DH/32, KH), dim3(32, 8)>>>(Ty);
    attn_kernel<<<dim3(NTOK/64, KH, BB), 256, ATTN_SMEM_BYTES>>>(mask);
    outgemm_kernel<<<dim3(CDIM/128, (BB*NTOK)/64), 256>>>(out);
}

// round 2
// speedup vs baseline: 1.0029x; 1.0029x over previous
#include <cuda_runtime.h>
#include <math.h>

// ---------------------------------------------------------------------------
// Problem constants (fixed by the dataset):
//   B=2 batch, N=2048 tokens, C=1024 model dim (P=Q=C), K=16 heads, D=64 head dim
// Pipeline:
//   Kp[b,k,m,d] = y'[b,m,:] . Lam_x[k,:,d]
//   Qp[b,k,n,d] = y'[b,n,:] . Lam_y[k,:,d]
//   Vp[b,k,m,d] = y'[b,m,:] . Th_x[k,:,d]
//   S[m,n] = (Kp[m].Qp[n] + mask[m,n]) / sqrt(D);  A = softmax over m
//   O[b,n,k,d] = sum_m A[m,n] Vp[m,d]
//   out[b,n,q] = sum_{k,d} O[b,n,k,d] * Th_y[k,q,d]
// ---------------------------------------------------------------------------

#define BB   2
#define NTOK 2048
#define CDIM 1024
#define KH   16
#define DH   64
#define KD   (KH*DH)          // 1024
#define INV_TEMP 0.125f       // 1/sqrt(64)

// Scratch (static __device__ arrays; no runtime allocation allowed)
__device__ float g_Kp[(size_t)BB*KH*NTOK*DH];   // 16 MB  [b][k][m][d]
__device__ float g_Qp[(size_t)BB*KH*NTOK*DH];   // 16 MB  [b][k][n][d]
__device__ float g_Vp[(size_t)BB*KH*NTOK*DH];   // 16 MB  [b][k][m][d]
__device__ float g_Ob[(size_t)BB*NTOK*KD];      // 16 MB  [b][n][k*64+d]
__device__ float g_Wt[(size_t)KD*CDIM];         //  4 MB  [k*64+d][q]

// ---------------------------------------------------------------------------
// Kernel 1: fused triple projection.  Block = (64 m-rows) x (192 cols = 3x64 d)
// for one (b,k).  256 threads; microtile 8 rows x 6 cols (cols = tx + 32*j).
// ---------------------------------------------------------------------------
__global__ __launch_bounds__(256) void proj_kernel(
    const float* __restrict__ y, const float* __restrict__ Lx,
    const float* __restrict__ Ly, const float* __restrict__ Tx)
{
    __shared__ float As[64][17];    // [m_local][kk]
    __shared__ float Bs[16][192];   // [kk][w*64+d]

    const int m0 = blockIdx.x * 64;
    const int k  = blockIdx.y;
    const int b  = blockIdx.z;
    const int t  = threadIdx.x;
    const int tx = t & 31;
    const int ty = t >> 5;

    float acc[8][6];
#pragma unroll
    for (int i = 0; i < 8; i++)
#pragma unroll
        for (int j = 0; j < 6; j++) acc[i][j] = 0.0f;

    const float* Aptr = y + (size_t)(b*NTOK + m0)*CDIM;
    const int ar  = t >> 2;
    const int ac4 = (t & 3) * 4;

    for (int kc = 0; kc < CDIM; kc += 16) {
        // Load A tile 64x16
        float4 av = *(const float4*)(Aptr + (size_t)ar*CDIM + kc + ac4);
        As[ar][ac4+0] = av.x; As[ar][ac4+1] = av.y;
        As[ar][ac4+2] = av.z; As[ar][ac4+3] = av.w;
        // Load B tile 16x192 (3 weight matrices, d contiguous)
#pragma unroll
        for (int s = 0; s < 3; s++) {
            int f   = t + 256*s;        // 0..767 float4 tiles
            int c   = f / 48;
            int rem = f - c*48;
            int w   = rem >> 4;
            int d4  = (rem & 15) * 4;
            const float* Wp = (w == 0) ? Lx : ((w == 1) ? Ly : Tx);
            float4 bv = *(const float4*)(Wp + ((size_t)(k*CDIM + kc + c))*DH + d4);
            *(float4*)&Bs[c][w*64 + d4] = bv;
        }
        __syncthreads();
#pragma unroll
        for (int kk = 0; kk < 16; kk++) {
            float a[8], bv[6];
#pragma unroll
            for (int i = 0; i < 8; i++) a[i] = As[ty*8 + i][kk];
#pragma unroll
            for (int j = 0; j < 6; j++) bv[j] = Bs[kk][tx + 32*j];
#pragma unroll
            for (int i = 0; i < 8; i++)
#pragma unroll
                for (int j = 0; j < 6; j++)
                    acc[i][j] = fmaf(a[i], bv[j], acc[i][j]);
        }
        __syncthreads();
    }

    const size_t base = ((size_t)((b*KH + k)*NTOK) + m0) * DH;
#pragma unroll
    for (int j = 0; j < 6; j++) {
        int c = tx + 32*j;
        int w = c >> 6;
        int d = c & 63;
        float* dst = (w == 0) ? g_Kp : ((w == 1) ? g_Qp : g_Vp);
#pragma unroll
        for (int i = 0; i < 8; i++)
            dst[base + (size_t)(ty*8 + i)*DH + d] = acc[i][j];
    }
}

// ---------------------------------------------------------------------------
// Kernel 2: flash attention per (b,k).  Block = 64 queries (n), loops over all
// m in tiles of 64.  256 threads as 16x16; 4x4 microtile.  Softmax row state
// (running max / sum) replicated in registers across each 16-lane row group.
// Dynamic smem: Qs[64][65] Ks[64][65] Vs[64][68] Ps[64][68]  (68096 B)
// ---------------------------------------------------------------------------
#define ATTN_SMEM_BYTES ((2*64*65 + 2*64*68) * 4)

__global__ __launch_bounds__(256) void attn_kernel(const float* __restrict__ mask)
{
    extern __shared__ float sm[];
    float* Qs = sm;                       // stride 65
    float* Ks = sm + 64*65;               // stride 65
    float* Vs = sm + 2*64*65;             // stride 68 (float4-aligned)
    float* Ps = sm + 2*64*65 + 64*68;     // stride 68 (float4-aligned)

    const int n0 = blockIdx.x * 64;
    const int k  = blockIdx.y;
    const int b  = blockIdx.z;
    const int t  = threadIdx.x;
    const int tx = t & 15;
    const int ty = t >> 4;

    const float* Qg = g_Qp + ((size_t)((b*KH + k)*NTOK) + n0)*DH;
    const float* Kg = g_Kp + (size_t)((b*KH + k)*NTOK)*DH;
    const float* Vg = g_Vp + (size_t)((b*KH + k)*NTOK)*DH;

    const int lr = t >> 2;          // 0..63 tile row for loads
    const int lcb = (t & 3) * 16;   // 16-float span per thread

    // Load Q tile once
#pragma unroll
    for (int u = 0; u < 4; u++) {
        int c4 = lcb + u*4;
        float4 v = *(const float4*)(Qg + (size_t)lr*DH + c4);
        Qs[lr*65 + c4+0] = v.x; Qs[lr*65 + c4+1] = v.y;
        Qs[lr*65 + c4+2] = v.z; Qs[lr*65 + c4+3] = v.w;
    }

    float Ot[4][4];
    float mprev[4], lsum[4];
#pragma unroll
    for (int i = 0; i < 4; i++) {
        mprev[i] = -1e30f; lsum[i] = 0.0f;
#pragma unroll
        for (int j = 0; j < 4; j++) Ot[i][j] = 0.0f;
    }

    for (int mt = 0; mt < NTOK/64; mt++) {
        __syncthreads();   // protects Ks/Vs/Ps from previous iteration readers
        const float* Kt = Kg + (size_t)mt*64*DH;
        const float* Vt = Vg + (size_t)mt*64*DH;
#pragma unroll
        for (int u = 0; u < 4; u++) {
            int c4 = lcb + u*4;
            float4 kv = *(const float4*)(Kt + (size_t)lr*DH + c4);
            Ks[lr*65 + c4+0] = kv.x; Ks[lr*65 + c4+1] = kv.y;
            Ks[lr*65 + c4+2] = kv.z; Ks[lr*65 + c4+3] = kv.w;
            float4 vv = *(const float4*)(Vt + (size_t)lr*DH + c4);
            *(float4*)&Vs[lr*68 + c4] = vv;
        }
        __syncthreads();

        // S tile: s[i][j] = Q[n0+ty*4+i] . K[mt*64+tx*4+j]
        float s[4][4];
#pragma unroll
        for (int i = 0; i < 4; i++)
#pragma unroll
            for (int j = 0; j < 4; j++) s[i][j] = 0.0f;
#pragma unroll 4
        for (int dd = 0; dd < 64; dd++) {
            float q[4], kk_[4];
#pragma unroll
            for (int i = 0; i < 4; i++) q[i]  = Qs[(ty*4 + i)*65 + dd];
#pragma unroll
            for (int j = 0; j < 4; j++) kk_[j] = Ks[(tx*4 + j)*65 + dd];
#pragma unroll
            for (int i = 0; i < 4; i++)
#pragma unroll
                for (int j = 0; j < 4; j++)
                    s[i][j] = fmaf(q[i], kk_[j], s[i][j]);
        }

        // mask (mask[m][n], n contiguous over i) + temperature
        const int mg = mt*64 + tx*4;
#pragma unroll
        for (int j = 0; j < 4; j++) {
            float4 mv = *(const float4*)(mask + (size_t)(mg + j)*NTOK + n0 + ty*4);
            s[0][j] = (s[0][j] + mv.x) * INV_TEMP;
            s[1][j] = (s[1][j] + mv.y) * INV_TEMP;
            s[2][j] = (s[2][j] + mv.z) * INV_TEMP;
            s[3][j] = (s[3][j] + mv.w) * INV_TEMP;
        }

        // Online softmax over m (reduce across the 16 lanes sharing a row group)
#pragma unroll
        for (int i = 0; i < 4; i++) {
            float rm = fmaxf(fmaxf(s[i][0], s[i][1]), fmaxf(s[i][2], s[i][3]));
            rm = fmaxf(rm, __shfl_xor_sync(0xffffffffu, rm, 1));
            rm = fmaxf(rm, __shfl_xor_sync(0xffffffffu, rm, 2));
            rm = fmaxf(rm, __shfl_xor_sync(0xffffffffu, rm, 4));
            rm = fmaxf(rm, __shfl_xor_sync(0xffffffffu, rm, 8));
            float mnew = fmaxf(mprev[i], rm);
            float corr = __expf(mprev[i] - mnew);
            lsum[i] *= corr;
#pragma unroll
            for (int j = 0; j < 4; j++) Ot[i][j] *= corr;
            float rs = 0.0f;
#pragma unroll
            for (int j = 0; j < 4; j++) {
                s[i][j] = __expf(s[i][j] - mnew);
                rs += s[i][j];
            }
            rs += __shfl_xor_sync(0xffffffffu, rs, 1);
            rs += __shfl_xor_sync(0xffffffffu, rs, 2);
            rs += __shfl_xor_sync(0xffffffffu, rs, 4);
            rs += __shfl_xor_sync(0xffffffffu, rs, 8);
            lsum[i] += rs;
            mprev[i] = mnew;
            *(float4*)&Ps[(ty*4 + i)*68 + tx*4] =
                make_float4(s[i][0], s[i][1], s[i][2], s[i][3]);
        }
        __syncthreads();

        // O += P @ V  (Ot cols j now index d = tx*4+j)
#pragma unroll 4
        for (int ml = 0; ml < 64; ml++) {
            float pv[4], vv[4];
#pragma unroll
            for (int i = 0; i < 4; i++) pv[i] = Ps[(ty*4 + i)*68 + ml];
#pragma unroll
            for (int j = 0; j < 4; j++) vv[j] = Vs[ml*68 + tx*4 + j];
#pragma unroll
            for (int i = 0; i < 4; i++)
#pragma unroll
                for (int j = 0; j < 4; j++)
                    Ot[i][j] = fmaf(pv[i], vv[j], Ot[i][j]);
        }
    }

    // Normalize + write O[b][n][k][d]
#pragma unroll
    for (int i = 0; i < 4; i++) {
        float inv = 1.0f / lsum[i];
        int n = n0 + ty*4 + i;
        float4 o = make_float4(Ot[i][0]*inv, Ot[i][1]*inv, Ot[i][2]*inv, Ot[i][3]*inv);
        *(float4*)(g_Ob + (((size_t)(b*NTOK + n))*KH + k)*DH + tx*4) = o;
    }
}

// ---------------------------------------------------------------------------
// Kernel 3: transpose Th_y [K][Q][D] -> g_Wt [k*64+d][q]
// ---------------------------------------------------------------------------
__global__ __launch_bounds__(256) void transpose_thy(const float* __restrict__ Ty)
{
    __shared__ float tile[32][33];
    const int q0 = blockIdx.x * 32;
    const int d0 = blockIdx.y * 32;
    const int k  = blockIdx.z;
    const int tx = threadIdx.x;     // 32
    const int ty = threadIdx.y;     // 8
#pragma unroll
    for (int s = 0; s < 4; s++) {
        int qq = ty + 8*s;
        tile[qq][tx] = Ty[((size_t)(k*CDIM + q0 + qq))*DH + d0 + tx];
    }
    __syncthreads();
#pragma unroll
    for (int s = 0; s < 4; s++) {
        int r = ty + 8*s;
        g_Wt[(size_t)(k*DH + d0 + r)*CDIM + q0 + tx] = tile[tx][r];
    }
}

// ---------------------------------------------------------------------------
// Kernel 4: output GEMM  out[bn][q] = g_Ob[bn][:] @ g_Wt[:][q]
// Block tile 64 x 128, 256 threads, microtile 8 rows x 4 cols (cols tx+32j).
// ---------------------------------------------------------------------------
__global__ __launch_bounds__(256) void outgemm_kernel(float* __restrict__ out)
{
    __shared__ float As[64][17];
    __shared__ float Bs[16][128];

    const int q0 = blockIdx.x * 128;
    const int m0 = blockIdx.y * 64;
    const int t  = threadIdx.x;
    const int tx = t & 31;
    const int ty = t >> 5;

    float acc[8][4];
#pragma unroll
    for (int i = 0; i < 8; i++)
#pragma unroll
        for (int j = 0; j < 4; j++) acc[i][j] = 0.0f;

    const int ar  = t >> 2;
    const int ac4 = (t & 3) * 4;

    for (int kc = 0; kc < KD; kc += 16) {
        float4 av = *(const float4*)(g_Ob + (size_t)(m0 + ar)*KD + kc + ac4);
        As[ar][ac4+0] = av.x; As[ar][ac4+1] = av.y;
        As[ar][ac4+2] = av.z; As[ar][ac4+3] = av.w;
#pragma unroll
        for (int s = 0; s < 2; s++) {
            int f  = t + 256*s;
            int c  = f >> 5;
            int q4 = (f & 31) * 4;
            *(float4*)&Bs[c][q4] =
                *(const float4*)(g_Wt + (size_t)(kc + c)*CDIM + q0 + q4);
        }
        __syncthreads();
#pragma unroll
        for (int kk = 0; kk < 16; kk++) {
            float a[8], bv[4];
#pragma unroll
            for (int i = 0; i < 8; i++) a[i] = As[ty*8 + i][kk];
#pragma unroll
            for (int j = 0; j < 4; j++) bv[j] = Bs[kk][tx + 32*j];
#pragma unroll
            for (int i = 0; i < 8; i++)
#pragma unroll
                for (int j = 0; j < 4; j++)
                    acc[i][j] = fmaf(a[i], bv[j], acc[i][j]);
        }
        __syncthreads();
    }
#pragma unroll
    for (int i = 0; i < 8; i++)
#pragma unroll
        for (int j = 0; j < 4; j++)
            out[(size_t)(m0 + ty*8 + i)*CDIM + q0 + tx + 32*j] = acc[i][j];
}

// ---------------------------------------------------------------------------
extern "C" void kernel_launch(void* const* d_in, const int* in_sizes, int n_in,
                              void* d_out, int out_size)
{
    (void)in_sizes; (void)n_in; (void)out_size;
    const float* y    = (const float*)d_in[0];
    const float* mask = (const float*)d_in[1];
    const float* Lx   = (const float*)d_in[2];
    const float* Ly   = (const float*)d_in[3];
    const float* Tx   = (const float*)d_in[4];
    const float* Ty   = (const float*)d_in[5];
    float* out = (float*)d_out;

    cudaFuncSetAttribute(attn_kernel,
        cudaFuncAttributeMaxDynamicSharedMemorySize, ATTN_SMEM_BYTES);

    proj_kernel<<<dim3(NTOK/64, KH, BB), 256>>>(y, Lx, Ly, Tx);
    transpose_thy<<<dim3(CDIM/32, DH/32, KH), dim3(32, 8)>>>(Ty);
    attn_kernel<<<dim3(NTOK/64, KH, BB), 256, ATTN_SMEM_BYTES>>>(mask);
    outgemm_kernel<<<dim3(CDIM/128, (BB*NTOK)/64), 256>>>(out);
}

// round 4
// speedup vs baseline: 2.1909x; 2.1846x over previous
#include <cuda_runtime.h>
#include <cuda_bf16.h>

typedef unsigned int u32; typedef unsigned short u16;

#define BB 2
#define NTOK 2048
#define CDIM 1024
#define NH 16
#define DH 64
#define KD 1024
#define SM_SCALE 0.18033688011112042f  // log2(e)/sqrt(64)
#define PAD 72

// scratch (static device arrays)
__device__ __nv_bfloat16 g_Yh[(size_t)BB*NTOK*CDIM];
__device__ __nv_bfloat16 g_Yl[(size_t)BB*NTOK*CDIM];
__device__ __nv_bfloat16 g_Wch[(size_t)NH*192*CDIM];   // [k][w*64+d][c]
__device__ __nv_bfloat16 g_Wcl[(size_t)NH*192*CDIM];
__device__ __nv_bfloat16 g_Kph[(size_t)BB*NH*NTOK*DH]; // [bk][m][d]
__device__ __nv_bfloat16 g_Kpl[(size_t)BB*NH*NTOK*DH];
__device__ __nv_bfloat16 g_Qph[(size_t)BB*NH*NTOK*DH];
__device__ __nv_bfloat16 g_Qpl[(size_t)BB*NH*NTOK*DH];
__device__ __nv_bfloat16 g_Vph[(size_t)BB*NH*NTOK*DH]; // [bk][m][d] token-major
__device__ __nv_bfloat16 g_Vpl[(size_t)BB*NH*NTOK*DH];
__device__ __nv_bfloat16 g_Ohh[(size_t)BB*NTOK*KD];    // [bn][k*64+d]
__device__ __nv_bfloat16 g_Oll[(size_t)BB*NTOK*KD];
__device__ __nv_bfloat16 g_W2h[(size_t)CDIM*KD];       // [q][k*64+d]
__device__ __nv_bfloat16 g_W2l[(size_t)CDIM*KD];

// ---------------- helpers ----------------------------------------------------
__device__ __forceinline__ u32 sptr(const void* p){
    u32 a; asm("{ .reg .u64 t; cvta.to.shared.u64 t, %1; cvt.u32.u64 %0, t; }" : "=r"(a) : "l"(p)); return a;
}
__device__ __forceinline__ void split1(float v, u16& h, u16& l){
    __nv_bfloat16 hb = __float2bfloat16(v);
    __nv_bfloat16 lb = __float2bfloat16(v - __bfloat162float(hb));
    h = __bfloat16_as_ushort(hb); l = __bfloat16_as_ushort(lb);
}
__device__ __forceinline__ void pack2(float x, float y, u32& hi, u32& lo){
    u16 hx,lx,hy,ly; split1(x,hx,lx); split1(y,hy,ly);
    hi = (u32)hx | ((u32)hy << 16); lo = (u32)lx | ((u32)ly << 16);
}
__device__ __forceinline__ float fexp2(float x){
    float y; asm("ex2.approx.ftz.f32 %0, %1;" : "=f"(y) : "f"(x)); return y;
}
__device__ __forceinline__ void mma16816(float* c, const u32* a, const u32* b){
    asm volatile("mma.sync.aligned.m16n8k16.row.col.f32.bf16.bf16.f32 "
        "{%0,%1,%2,%3}, {%4,%5,%6,%7}, {%8,%9}, {%0,%1,%2,%3};"
        : "+f"(c[0]), "+f"(c[1]), "+f"(c[2]), "+f"(c[3])
        : "r"(a[0]), "r"(a[1]), "r"(a[2]), "r"(a[3]), "r"(b[0]), "r"(b[1]));
}
__device__ __forceinline__ void ldsm4(u32* r, u32 a){
    asm volatile("ldmatrix.sync.aligned.m8n8.x4.shared.b16 {%0,%1,%2,%3}, [%4];"
        : "=r"(r[0]), "=r"(r[1]), "=r"(r[2]), "=r"(r[3]) : "r"(a));
}
__device__ __forceinline__ void ldsm4t(u32* r, u32 a){
    asm volatile("ldmatrix.sync.aligned.m8n8.x4.trans.shared.b16 {%0,%1,%2,%3}, [%4];"
        : "=r"(r[0]), "=r"(r[1]), "=r"(r[2]), "=r"(r[3]) : "r"(a));
}

// ---------------- prep kernels ------------------------------------------------
__global__ __launch_bounds__(256) void split_y_k(const float* __restrict__ y){
    size_t i = ((size_t)blockIdx.x*256 + threadIdx.x) * 4;
    float4 v = *(const float4*)(y + i);
    u32 h01,l01,h23,l23;
    pack2(v.x, v.y, h01, l01); pack2(v.z, v.w, h23, l23);
    *(uint2*)(g_Yh + i) = make_uint2(h01, h23);
    *(uint2*)(g_Yl + i) = make_uint2(l01, l23);
}
__global__ __launch_bounds__(256) void wcat_k(const float* __restrict__ Lx,
        const float* __restrict__ Ly, const float* __restrict__ Tx){
    __shared__ float t[32][33];
    int k = blockIdx.z / 3, w = blockIdx.z % 3;
    const float* src = (w == 0) ? Lx : ((w == 1) ? Ly : Tx);
    int c0 = blockIdx.x * 32, d0 = blockIdx.y * 32;
    int tx = threadIdx.x, ty = threadIdx.y;
#pragma unroll
    for (int s = 0; s < 4; s++)
        t[ty + 8*s][tx] = src[((size_t)k*CDIM + c0 + ty + 8*s)*DH + d0 + tx];
    __syncthreads();
#pragma unroll
    for (int s = 0; s < 4; s++){
        int r = ty + 8*s;
        u16 h,l; split1(t[tx][r], h, l);
        size_t o = ((size_t)k*192 + w*64 + d0 + r)*CDIM + c0 + tx;
        g_Wch[o] = __ushort_as_bfloat16(h);
        g_Wcl[o] = __ushort_as_bfloat16(l);
    }
}
__global__ __launch_bounds__(256) void wout_k(const float* __restrict__ Ty){
    size_t i = ((size_t)blockIdx.x*256 + threadIdx.x) * 4;
    int k = (int)(i >> 16), q = (int)((i >> 6) & 1023), d = (int)(i & 63);
    float4 v = *(const float4*)(Ty + i);
    u32 h01,l01,h23,l23;
    pack2(v.x, v.y, h01, l01); pack2(v.z, v.w, h23, l23);
    size_t o = (size_t)q*KD + (size_t)k*64 + d;
    *(uint2*)(g_W2h + o) = make_uint2(h01, h23);
    *(uint2*)(g_W2l + o) = make_uint2(l01, l23);
}

// ---------------- projection: D[128 x 192] = Y[128 x 1024] @ Wcat^T ----------
#define PROJ_SMEM (640*PAD*2)
__global__ __launch_bounds__(256) void proj_h(){
    extern __shared__ __nv_bfloat16 sm[];
    __nv_bfloat16 *Ah = sm, *Al = Ah + 128*PAD, *Bh = Al + 128*PAD, *Bl = Bh + 192*PAD;
    const int t = threadIdx.x, lane = t & 31, w = t >> 5;
    const int wm = w & 1, wn = w >> 1;      // 2 x 4 warps; warp tile 64m x 48n
    const int m0 = blockIdx.x*128, k = blockIdx.y, b = blockIdx.z;
    const size_t bk = (size_t)(b*NH + k);
    const __nv_bfloat16 *Ygh = g_Yh + (size_t)(b*NTOK + m0)*CDIM;
    const __nv_bfloat16 *Ygl = g_Yl + (size_t)(b*NTOK + m0)*CDIM;
    const __nv_bfloat16 *Wgh = g_Wch + (size_t)k*192*CDIM;
    const __nv_bfloat16 *Wgl = g_Wcl + (size_t)k*192*CDIM;

    float acc[4][6][4];
#pragma unroll
    for (int i=0;i<4;i++)
#pragma unroll
    for (int j=0;j<6;j++)
#pragma unroll
    for (int e=0;e<4;e++) acc[i][j][e]=0.f;

    const int arow = lane & 15, acolh = (lane >> 4) << 3;
    const int brow = (lane & 7) + ((lane & 16) >> 1), bcolh = lane & 8;

    for (int kc = 0; kc < CDIM; kc += 64){
        __syncthreads();
        for (int i = t; i < 2048; i += 256){
            int arr = i >> 10, idx = i & 1023, r = idx >> 3, c8 = (idx & 7)*8;
            const __nv_bfloat16* src = (arr ? Ygl : Ygh) + (size_t)r*CDIM + kc + c8;
            *(uint4*)((arr ? Al : Ah) + r*PAD + c8) = *(const uint4*)src;
        }
        for (int i = t; i < 3072; i += 256){
            int arr = i >= 1536, idx = arr ? i - 1536 : i, r = idx >> 3, c8 = (idx & 7)*8;
            const __nv_bfloat16* src = (arr ? Wgl : Wgh) + (size_t)r*CDIM + kc + c8;
            *(uint4*)((arr ? Bl : Bh) + r*PAD + c8) = *(const uint4*)src;
        }
        __syncthreads();
#pragma unroll
        for (int ks = 0; ks < 4; ks++){
            u32 ah[4][4], al2[4][4], bh[3][4], bl2[3][4];
#pragma unroll
            for (int mt = 0; mt < 4; mt++){
                int ro = (wm*64 + mt*16 + arow)*PAD + ks*16 + acolh;
                ldsm4(ah[mt],  sptr(Ah + ro));
                ldsm4(al2[mt], sptr(Al + ro));
            }
#pragma unroll
            for (int p = 0; p < 3; p++){
                int ro = (wn*48 + p*16 + brow)*PAD + ks*16 + bcolh;
                ldsm4(bh[p],  sptr(Bh + ro));
                ldsm4(bl2[p], sptr(Bl + ro));
            }
#pragma unroll
            for (int mt = 0; mt < 4; mt++)
#pragma unroll
            for (int p = 0; p < 3; p++){
                mma16816(acc[mt][2*p],   ah[mt],  &bh[p][0]);
                mma16816(acc[mt][2*p+1], ah[mt],  &bh[p][2]);
                mma16816(acc[mt][2*p],   ah[mt],  &bl2[p][0]);
                mma16816(acc[mt][2*p+1], ah[mt],  &bl2[p][2]);
                mma16816(acc[mt][2*p],   al2[mt], &bh[p][0]);
                mma16816(acc[mt][2*p+1], al2[mt], &bh[p][2]);
            }
        }
    }
    // epilogue: split-store to K/Q/V (all token-major [m][64])
#pragma unroll
    for (int mt = 0; mt < 4; mt++)
#pragma unroll
    for (int nt = 0; nt < 6; nt++){
        int cbase = wn*48 + nt*8 + 2*(lane & 3);
        int wsel = cbase >> 6, d = cbase & 63;
        __nv_bfloat16* dh = (wsel == 0) ? g_Kph : (wsel == 1) ? g_Qph : g_Vph;
        __nv_bfloat16* dl = (wsel == 0) ? g_Kpl : (wsel == 1) ? g_Qpl : g_Vpl;
#pragma unroll
        for (int h = 0; h < 2; h++){
            int m = m0 + wm*64 + mt*16 + (lane >> 2) + h*8;
            u32 hi, lo; pack2(acc[mt][nt][h*2], acc[mt][nt][h*2+1], hi, lo);
            size_t off = (bk*NTOK + m)*DH + d;
            *(u32*)(dh + off) = hi;
            *(u32*)(dl + off) = lo;
        }
    }
}

// ---------------- attention: 128 queries/CTA, 64-key chunks ------------------
#define ATT_SMEM (512*PAD*2)
__global__ __launch_bounds__(256) void attn_h(const float* __restrict__ mask){
    extern __shared__ __nv_bfloat16 sm[];
    __nv_bfloat16 *Qh = sm, *Ql = Qh + 128*PAD, *Kh = Ql + 128*PAD,
                  *Kl = Kh + 64*PAD, *Vh = Kl + 64*PAD, *Vl = Vh + 64*PAD;
    const int t = threadIdx.x, lane = t & 31, w = t >> 5;
    const int wn = w & 3, wm = w >> 2;      // 4(n) x 2(m); warp 32n x 32m
    const int n0 = blockIdx.x*128, k = blockIdx.y, b = blockIdx.z;
    const size_t bk = (size_t)(b*NH + k);

    // load Q tiles once
    for (int i = t; i < 2048; i += 256){
        int arr = i >> 10, idx = i & 1023, r = idx >> 3, c8 = (idx & 7)*8;
        const __nv_bfloat16* src = (arr ? g_Qpl : g_Qph) + (bk*NTOK + n0 + r)*DH + c8;
        *(uint4*)((arr ? Ql : Qh) + r*PAD + c8) = *(const uint4*)src;
    }

    const float* mp[4]; float rsum[4];
#pragma unroll
    for (int j = 0; j < 4; j++){
        int nl = wn*32 + (j >> 1)*16 + (lane >> 2) + (j & 1)*8;
        mp[j] = mask + n0 + nl;
        rsum[j] = 0.f;
    }
    float Oacc[2][8][4];
#pragma unroll
    for (int i=0;i<2;i++)
#pragma unroll
    for (int j=0;j<8;j++)
#pragma unroll
    for (int e=0;e<4;e++) Oacc[i][j][e]=0.f;

    const int arow = lane & 15, acolh = (lane >> 4) << 3;
    const int brow = (lane & 7) + ((lane & 16) >> 1), bcolh = lane & 8;
    const int vrow = (lane & 7) + (lane & 8), vcolh = (lane & 16) >> 1;

    for (int mc = 0; mc < NTOK; mc += 64){
        __syncthreads();
        for (int i = t; i < 2048; i += 256){
            int arr = i >> 9, idx = i & 511, r = idx >> 3, c8 = (idx & 7)*8;
            const __nv_bfloat16* src =
                ((arr == 0) ? g_Kph : (arr == 1) ? g_Kpl : (arr == 2) ? g_Vph : g_Vpl)
                + (bk*NTOK + mc + r)*DH + c8;
            __nv_bfloat16* dst =
                ((arr == 0) ? Kh : (arr == 1) ? Kl : (arr == 2) ? Vh : Vl) + r*PAD + c8;
            *(uint4*)dst = *(const uint4*)src;
        }
        __syncthreads();

        float S[2][4][4];
#pragma unroll
        for (int i=0;i<2;i++)
#pragma unroll
        for (int j=0;j<4;j++)
#pragma unroll
        for (int e=0;e<4;e++) S[i][j][e]=0.f;
#pragma unroll
        for (int ks = 0; ks < 4; ks++){
            u32 qh[2][4], ql2[2][4], kh2[2][4], kl2[2][4];
#pragma unroll
            for (int nt = 0; nt < 2; nt++){
                int ro = (wn*32 + nt*16 + arow)*PAD + ks*16 + acolh;
                ldsm4(qh[nt],  sptr(Qh + ro));
                ldsm4(ql2[nt], sptr(Ql + ro));
            }
#pragma unroll
            for (int p = 0; p < 2; p++){
                int ro = (wm*32 + p*16 + brow)*PAD + ks*16 + bcolh;
                ldsm4(kh2[p], sptr(Kh + ro));
                ldsm4(kl2[p], sptr(Kl + ro));
            }
#pragma unroll
            for (int nt = 0; nt < 2; nt++)
#pragma unroll
            for (int p = 0; p < 2; p++){
                mma16816(S[nt][2*p],   qh[nt],  &kh2[p][0]);
                mma16816(S[nt][2*p+1], qh[nt],  &kh2[p][2]);
                mma16816(S[nt][2*p],   qh[nt],  &kl2[p][0]);
                mma16816(S[nt][2*p+1], qh[nt],  &kl2[p][2]);
                mma16816(S[nt][2*p],   ql2[nt], &kh2[p][0]);
                mma16816(S[nt][2*p+1], ql2[nt], &kh2[p][2]);
            }
        }
        // softmax (no max-subtraction; logits are small) + pack P fragments
        u32 ph[2][2][4], pl2[2][2][4];
#pragma unroll
        for (int nt = 0; nt < 2; nt++){
#pragma unroll
            for (int mt = 0; mt < 4; mt++)
#pragma unroll
            for (int e = 0; e < 4; e++){
                int m = mc + wm*32 + mt*8 + 2*(lane & 3) + (e & 1);
                float mval = mp[nt*2 + (e >> 1)][(size_t)m * NTOK];
                float p = fexp2((S[nt][mt][e] + mval) * SM_SCALE);
                rsum[nt*2 + (e >> 1)] += p;
                S[nt][mt][e] = p;
            }
#pragma unroll
            for (int kp = 0; kp < 2; kp++){
                pack2(S[nt][2*kp][0],   S[nt][2*kp][1],   ph[nt][kp][0], pl2[nt][kp][0]);
                pack2(S[nt][2*kp][2],   S[nt][2*kp][3],   ph[nt][kp][1], pl2[nt][kp][1]);
                pack2(S[nt][2*kp+1][0], S[nt][2*kp+1][1], ph[nt][kp][2], pl2[nt][kp][2]);
                pack2(S[nt][2*kp+1][2], S[nt][2*kp+1][3], ph[nt][kp][3], pl2[nt][kp][3]);
            }
        }
        // O += P @ V
#pragma unroll
        for (int kp = 0; kp < 2; kp++){
            u32 vh2[4][4], vl2[4][4];
#pragma unroll
            for (int pd = 0; pd < 4; pd++){
                int ro = (wm*32 + kp*16 + vrow)*PAD + pd*16 + vcolh;
                ldsm4t(vh2[pd], sptr(Vh + ro));
                ldsm4t(vl2[pd], sptr(Vl + ro));
            }
#pragma unroll
            for (int nt = 0; nt < 2; nt++)
#pragma unroll
            for (int pd = 0; pd < 4; pd++){
                mma16816(Oacc[nt][2*pd],   ph[nt][kp],  &vh2[pd][0]);
                mma16816(Oacc[nt][2*pd+1], ph[nt][kp],  &vh2[pd][2]);
                mma16816(Oacc[nt][2*pd],   ph[nt][kp],  &vl2[pd][0]);
                mma16816(Oacc[nt][2*pd+1], ph[nt][kp],  &vl2[pd][2]);
                mma16816(Oacc[nt][2*pd],   pl2[nt][kp], &vh2[pd][0]);
                mma16816(Oacc[nt][2*pd+1], pl2[nt][kp], &vh2[pd][2]);
            }
        }
    }
    // epilogue: cross-warp (wm) reduce + rowsum normalize + split store
    __syncthreads();
    float* Osm  = (float*)sm;          // [128][65]
    float* rssm = Osm + 128*65;        // [128][8]
#pragma unroll
    for (int j = 0; j < 4; j++){
        int nl = wn*32 + (j >> 1)*16 + (lane >> 2) + (j & 1)*8;
        rssm[nl*8 + wm*4 + (lane & 3)] = rsum[j];
    }
    if (wm == 1){
#pragma unroll
        for (int nt = 0; nt < 2; nt++)
#pragma unroll
        for (int dt = 0; dt < 8; dt++)
#pragma unroll
        for (int e = 0; e < 4; e++){
            int nl = wn*32 + nt*16 + (lane >> 2) + (e >> 1)*8;
            int d  = dt*8 + 2*(lane & 3) + (e & 1);
            Osm[nl*65 + d] = Oacc[nt][dt][e];
        }
    }
    __syncthreads();
    if (wm == 0){
        float inv[4];
#pragma unroll
        for (int j = 0; j < 4; j++){
            int nl = wn*32 + (j >> 1)*16 + (lane >> 2) + (j & 1)*8;
            float s = 0.f;
#pragma unroll
            for (int q = 0; q < 8; q++) s += rssm[nl*8 + q];
            inv[j] = 1.0f / s;
        }
#pragma unroll
        for (int nt = 0; nt < 2; nt++)
#pragma unroll
        for (int dt = 0; dt < 8; dt++)
#pragma unroll
        for (int h = 0; h < 2; h++){
            int nl = wn*32 + nt*16 + (lane >> 2) + h*8;
            int d  = dt*8 + 2*(lane & 3);
            float iv = inv[nt*2 + h];
            float v0 = (Oacc[nt][dt][h*2]   + Osm[nl*65 + d])     * iv;
            float v1 = (Oacc[nt][dt][h*2+1] + Osm[nl*65 + d + 1]) * iv;
            u32 hi, lo; pack2(v0, v1, hi, lo);
            size_t off = ((size_t)(b*NTOK + n0 + nl))*KD + (size_t)k*DH + d;
            *(u32*)(g_Ohh + off) = hi;
            *(u32*)(g_Oll + off) = lo;
        }
    }
}

// ---------------- output GEMM: out[128 x 128] = O[128 x 1024] @ W2^T ---------
#define OUT_SMEM (512*PAD*2)
__global__ __launch_bounds__(256) void out_h(float* __restrict__ out){
    extern __shared__ __nv_bfloat16 sm[];
    __nv_bfloat16 *Ah = sm, *Al = Ah + 128*PAD, *Bh = Al + 128*PAD, *Bl = Bh + 128*PAD;
    const int t = threadIdx.x, lane = t & 31, w = t >> 5;
    const int wm = w & 1, wn = w >> 1;      // 2 x 4; warp 64m x 32n
    const int q0 = blockIdx.x*128, r0 = blockIdx.y*128;

    float acc[4][4][4];
#pragma unroll
    for (int i=0;i<4;i++)
#pragma unroll
    for (int j=0;j<4;j++)
#pragma unroll
    for (int e=0;e<4;e++) acc[i][j][e]=0.f;

    const int arow = lane & 15, acolh = (lane >> 4) << 3;
    const int brow = (lane & 7) + ((lane & 16) >> 1), bcolh = lane & 8;

    for (int kc = 0; kc < KD; kc += 64){
        __syncthreads();
        for (int i = t; i < 2048; i += 256){
            int arr = i >> 10, idx = i & 1023, r = idx >> 3, c8 = (idx & 7)*8;
            const __nv_bfloat16* src = (arr ? g_Oll : g_Ohh) + (size_t)(r0 + r)*KD + kc + c8;
            *(uint4*)((arr ? Al : Ah) + r*PAD + c8) = *(const uint4*)src;
        }
        for (int i = t; i < 2048; i += 256){
            int arr = i >> 10, idx = i & 1023, r = idx >> 3, c8 = (idx & 7)*8;
            const __nv_bfloat16* src = (arr ? g_W2l : g_W2h) + (size_t)(q0 + r)*KD + kc + c8;
            *(uint4*)((arr ? Bl : Bh) + r*PAD + c8) = *(const uint4*)src;
        }
        __syncthreads();
#pragma unroll
        for (int ks = 0; ks < 4; ks++){
            u32 ah[4][4], al2[4][4], bh[2][4], bl2[2][4];
#pragma unroll
            for (int mt = 0; mt < 4; mt++){
                int ro = (wm*64 + mt*16 + arow)*PAD + ks*16 + acolh;
                ldsm4(ah[mt],  sptr(Ah + ro));
                ldsm4(al2[mt], sptr(Al + ro));
            }
#pragma unroll
            for (int p = 0; p < 2; p++){
                int ro = (wn*32 + p*16 + brow)*PAD + ks*16 + bcolh;
                ldsm4(bh[p],  sptr(Bh + ro));
                ldsm4(bl2[p], sptr(Bl + ro));
            }
#pragma unroll
            for (int mt = 0; mt < 4; mt++)
#pragma unroll
            for (int p = 0; p < 2; p++){
                mma16816(acc[mt][2*p],   ah[mt],  &bh[p][0]);
                mma16816(acc[mt][2*p+1], ah[mt],  &bh[p][2]);
                mma16816(acc[mt][2*p],   ah[mt],  &bl2[p][0]);
                mma16816(acc[mt][2*p+1], ah[mt],  &bl2[p][2]);
                mma16816(acc[mt][2*p],   al2[mt], &bh[p][0]);
                mma16816(acc[mt][2*p+1], al2[mt], &bh[p][2]);
            }
        }
    }
#pragma unroll
    for (int mt = 0; mt < 4; mt++)
#pragma unroll
    for (int nt = 0; nt < 4; nt++)
#pragma unroll
    for (int h = 0; h < 2; h++){
        int r = r0 + wm*64 + mt*16 + (lane >> 2) + h*8;
        int c = q0 + wn*32 + nt*8 + 2*(lane & 3);
        *(float2*)(out + (size_t)r*CDIM + c) =
            make_float2(acc[mt][nt][h*2], acc[mt][nt][h*2+1]);
    }
}

// -----------------------------------------------------------------------------
extern "C" void kernel_launch(void* const* d_in, const int* in_sizes, int n_in,
                              void* d_out, int out_size)
{
    (void)in_sizes; (void)n_in; (void)out_size;
    const float* y    = (const float*)d_in[0];
    const float* mask = (const float*)d_in[1];
    const float* Lx   = (const float*)d_in[2];
    const float* Ly   = (const float*)d_in[3];
    const float* Tx   = (const float*)d_in[4];
    const float* Ty   = (const float*)d_in[5];
    float* out = (float*)d_out;

    cudaFuncSetAttribute(proj_h, cudaFuncAttributeMaxDynamicSharedMemorySize, PROJ_SMEM);
    cudaFuncSetAttribute(attn_h, cudaFuncAttributeMaxDynamicSharedMemorySize, ATT_SMEM);
    cudaFuncSetAttribute(out_h,  cudaFuncAttributeMaxDynamicSharedMemorySize, OUT_SMEM);

    split_y_k<<<4096, 256>>>(y);
    wcat_k<<<dim3(32, 2, 48), dim3(32, 8)>>>(Lx, Ly, Tx);
    wout_k<<<1024, 256>>>(Ty);
    proj_h<<<dim3(NTOK/128, NH, BB), 256, PROJ_SMEM>>>();
    attn_h<<<dim3(NTOK/128, NH, BB), 256, ATT_SMEM>>>(mask);
    out_h<<<dim3(CDIM/128, (BB*NTOK)/128), 256, OUT_SMEM>>>(out);
}

// round 5
// speedup vs baseline: 2.6809x; 1.2236x over previous
#include <cuda_runtime.h>
#include <cuda_bf16.h>

typedef unsigned int u32; typedef unsigned short u16;

#define BB 2
#define NTOK 2048
#define CDIM 1024
#define NH 16
#define DH 64
#define KD 1024
#define SM_SCALE 0.18033688011112042f  // log2(e)/sqrt(64)
#define PAD 72

// scratch (static device arrays)
__device__ __nv_bfloat16 g_Yh[(size_t)BB*NTOK*CDIM];
__device__ __nv_bfloat16 g_Yl[(size_t)BB*NTOK*CDIM];
__device__ __nv_bfloat16 g_Wch[(size_t)NH*192*CDIM];   // [k][w*64+d][c]
__device__ __nv_bfloat16 g_Wcl[(size_t)NH*192*CDIM];
__device__ __nv_bfloat16 g_Kph[(size_t)BB*NH*NTOK*DH]; // [bk][m][d]
__device__ __nv_bfloat16 g_Kpl[(size_t)BB*NH*NTOK*DH];
__device__ __nv_bfloat16 g_Qph[(size_t)BB*NH*NTOK*DH];
__device__ __nv_bfloat16 g_Qpl[(size_t)BB*NH*NTOK*DH];
__device__ __nv_bfloat16 g_Vph[(size_t)BB*NH*NTOK*DH];
__device__ __nv_bfloat16 g_Vpl[(size_t)BB*NH*NTOK*DH];
__device__ __nv_bfloat16 g_Ohh[(size_t)BB*NTOK*KD];    // [bn][k*64+d]
__device__ __nv_bfloat16 g_Oll[(size_t)BB*NTOK*KD];
__device__ __nv_bfloat16 g_W2h[(size_t)CDIM*KD];       // [q][k*64+d]
__device__ __nv_bfloat16 g_W2l[(size_t)CDIM*KD];

// ---------------- helpers ----------------------------------------------------
__device__ __forceinline__ u32 sptr(const void* p){
    u32 a; asm("{ .reg .u64 t; cvta.to.shared.u64 t, %1; cvt.u32.u64 %0, t; }" : "=r"(a) : "l"(p)); return a;
}
#define CPA(dst, src) asm volatile("cp.async.cg.shared.global [%0], [%1], 16;" :: "r"(dst), "l"(src))
#define CPC()  asm volatile("cp.async.commit_group;" ::: "memory")
#define CPW0() asm volatile("cp.async.wait_group 0;" ::: "memory")

__device__ __forceinline__ void split1(float v, u16& h, u16& l){
    __nv_bfloat16 hb = __float2bfloat16(v);
    __nv_bfloat16 lb = __float2bfloat16(v - __bfloat162float(hb));
    h = __bfloat16_as_ushort(hb); l = __bfloat16_as_ushort(lb);
}
__device__ __forceinline__ void pack2(float x, float y, u32& hi, u32& lo){
    u16 hx,lx,hy,ly; split1(x,hx,lx); split1(y,hy,ly);
    hi = (u32)hx | ((u32)hy << 16); lo = (u32)lx | ((u32)ly << 16);
}
__device__ __forceinline__ float fexp2(float x){
    float y; asm("ex2.approx.ftz.f32 %0, %1;" : "=f"(y) : "f"(x)); return y;
}
__device__ __forceinline__ void mma16816(float* c, const u32* a, const u32* b){
    asm volatile("mma.sync.aligned.m16n8k16.row.col.f32.bf16.bf16.f32 "
        "{%0,%1,%2,%3}, {%4,%5,%6,%7}, {%8,%9}, {%0,%1,%2,%3};"
        : "+f"(c[0]), "+f"(c[1]), "+f"(c[2]), "+f"(c[3])
        : "r"(a[0]), "r"(a[1]), "r"(a[2]), "r"(a[3]), "r"(b[0]), "r"(b[1]));
}
__device__ __forceinline__ void ldsm4(u32* r, u32 a){
    asm volatile("ldmatrix.sync.aligned.m8n8.x4.shared.b16 {%0,%1,%2,%3}, [%4];"
        : "=r"(r[0]), "=r"(r[1]), "=r"(r[2]), "=r"(r[3]) : "r"(a));
}
__device__ __forceinline__ void ldsm4t(u32* r, u32 a){
    asm volatile("ldmatrix.sync.aligned.m8n8.x4.trans.shared.b16 {%0,%1,%2,%3}, [%4];"
        : "=r"(r[0]), "=r"(r[1]), "=r"(r[2]), "=r"(r[3]) : "r"(a));
}

// ---------------- prep kernels ------------------------------------------------
__global__ __launch_bounds__(256) void split_y_k(const float* __restrict__ y){
    size_t i = ((size_t)blockIdx.x*256 + threadIdx.x) * 4;
    float4 v = *(const float4*)(y + i);
    u32 h01,l01,h23,l23;
    pack2(v.x, v.y, h01, l01); pack2(v.z, v.w, h23, l23);
    *(uint2*)(g_Yh + i) = make_uint2(h01, h23);
    *(uint2*)(g_Yl + i) = make_uint2(l01, l23);
}
__global__ __launch_bounds__(256) void wcat_k(const float* __restrict__ Lx,
        const float* __restrict__ Ly, const float* __restrict__ Tx){
    __shared__ float t[32][33];
    int k = blockIdx.z / 3, w = blockIdx.z % 3;
    const float* src = (w == 0) ? Lx : ((w == 1) ? Ly : Tx);
    int c0 = blockIdx.x * 32, d0 = blockIdx.y * 32;
    int tx = threadIdx.x, ty = threadIdx.y;
#pragma unroll
    for (int s = 0; s < 4; s++)
        t[ty + 8*s][tx] = src[((size_t)k*CDIM + c0 + ty + 8*s)*DH + d0 + tx];
    __syncthreads();
#pragma unroll
    for (int s = 0; s < 4; s++){
        int r = ty + 8*s;
        u16 h,l; split1(t[tx][r], h, l);
        size_t o = ((size_t)k*192 + w*64 + d0 + r)*CDIM + c0 + tx;
        g_Wch[o] = __ushort_as_bfloat16(h);
        g_Wcl[o] = __ushort_as_bfloat16(l);
    }
}
__global__ __launch_bounds__(256) void wout_k(const float* __restrict__ Ty){
    size_t i = ((size_t)blockIdx.x*256 + threadIdx.x) * 4;
    int k = (int)(i >> 16), q = (int)((i >> 6) & 1023), d = (int)(i & 63);
    float4 v = *(const float4*)(Ty + i);
    u32 h01,l01,h23,l23;
    pack2(v.x, v.y, h01, l01); pack2(v.z, v.w, h23, l23);
    size_t o = (size_t)q*KD + (size_t)k*64 + d;
    *(uint2*)(g_W2h + o) = make_uint2(h01, h23);
    *(uint2*)(g_W2l + o) = make_uint2(l01, l23);
}

// ---------------- projection: D[128 x 192] = Y[128 x 1024] @ Wcat^T ----------
#define PROJ_BUF (640*PAD)
#define PROJ_SMEM (2*PROJ_BUF*2)
__global__ __launch_bounds__(256) void proj_h(){
    extern __shared__ __nv_bfloat16 sm[];
    const int t = threadIdx.x, lane = t & 31, w = t >> 5;
    const int wm = w & 1, wn = w >> 1;      // 2 x 4 warps; warp tile 64m x 48n
    const int m0 = blockIdx.x*128, k = blockIdx.y, b = blockIdx.z;
    const size_t bk = (size_t)(b*NH + k);
    const __nv_bfloat16 *Ygh = g_Yh + (size_t)(b*NTOK + m0)*CDIM;
    const __nv_bfloat16 *Ygl = g_Yl + (size_t)(b*NTOK + m0)*CDIM;
    const __nv_bfloat16 *Wgh = g_Wch + (size_t)k*192*CDIM;
    const __nv_bfloat16 *Wgl = g_Wcl + (size_t)k*192*CDIM;

    float acc[4][6][4];
#pragma unroll
    for (int i=0;i<4;i++)
#pragma unroll
    for (int j=0;j<6;j++)
#pragma unroll
    for (int e=0;e<4;e++) acc[i][j][e]=0.f;

    const int arow = lane & 15, acolh = (lane >> 4) << 3;
    const int brow = (lane & 7) + ((lane & 16) >> 1), bcolh = lane & 8;

    auto issue = [&](int kc, int pb){
        __nv_bfloat16* base = sm + pb*PROJ_BUF;
        for (int i = t; i < 2048; i += 256){
            int arr = i >> 10, idx = i & 1023, r = idx >> 3, c8 = (idx & 7)*8;
            const __nv_bfloat16* src = (arr ? Ygl : Ygh) + (size_t)r*CDIM + kc + c8;
            CPA(sptr(base + arr*128*PAD + r*PAD + c8), src);
        }
        for (int i = t; i < 3072; i += 256){
            int arr = i >= 1536, idx = arr ? i - 1536 : i, r = idx >> 3, c8 = (idx & 7)*8;
            const __nv_bfloat16* src = (arr ? Wgl : Wgh) + (size_t)r*CDIM + kc + c8;
            CPA(sptr(base + 256*PAD + arr*192*PAD + r*PAD + c8), src);
        }
        CPC();
    };

    issue(0, 0);
    for (int it = 0; it < 16; it++){
        CPW0(); __syncthreads();
        if (it + 1 < 16) issue((it + 1)*64, (it + 1) & 1);
        __nv_bfloat16* base = sm + (it & 1)*PROJ_BUF;
        __nv_bfloat16 *Ah = base, *Al = base + 128*PAD,
                      *Bh = base + 256*PAD, *Bl = base + 448*PAD;
#pragma unroll
        for (int ks = 0; ks < 4; ks++){
            u32 ah[4][4], al2[4][4], bh[3][4], bl2[3][4];
#pragma unroll
            for (int mt = 0; mt < 4; mt++){
                int ro = (wm*64 + mt*16 + arow)*PAD + ks*16 + acolh;
                ldsm4(ah[mt],  sptr(Ah + ro));
                ldsm4(al2[mt], sptr(Al + ro));
            }
#pragma unroll
            for (int p = 0; p < 3; p++){
                int ro = (wn*48 + p*16 + brow)*PAD + ks*16 + bcolh;
                ldsm4(bh[p],  sptr(Bh + ro));
                ldsm4(bl2[p], sptr(Bl + ro));
            }
#pragma unroll
            for (int mt = 0; mt < 4; mt++)
#pragma unroll
            for (int p = 0; p < 3; p++){
                mma16816(acc[mt][2*p],   ah[mt],  &bh[p][0]);
                mma16816(acc[mt][2*p+1], ah[mt],  &bh[p][2]);
                mma16816(acc[mt][2*p],   ah[mt],  &bl2[p][0]);
                mma16816(acc[mt][2*p+1], ah[mt],  &bl2[p][2]);
                mma16816(acc[mt][2*p],   al2[mt], &bh[p][0]);
                mma16816(acc[mt][2*p+1], al2[mt], &bh[p][2]);
            }
        }
    }
    // epilogue: split-store to K/Q/V (token-major [m][64])
#pragma unroll
    for (int mt = 0; mt < 4; mt++)
#pragma unroll
    for (int nt = 0; nt < 6; nt++){
        int cbase = wn*48 + nt*8 + 2*(lane & 3);
        int wsel = cbase >> 6, d = cbase & 63;
        __nv_bfloat16* dh = (wsel == 0) ? g_Kph : (wsel == 1) ? g_Qph : g_Vph;
        __nv_bfloat16* dl = (wsel == 0) ? g_Kpl : (wsel == 1) ? g_Qpl : g_Vpl;
#pragma unroll
        for (int h = 0; h < 2; h++){
            int m = m0 + wm*64 + mt*16 + (lane >> 2) + h*8;
            u32 hi, lo; pack2(acc[mt][nt][h*2], acc[mt][nt][h*2+1], hi, lo);
            size_t off = (bk*NTOK + m)*DH + d;
            *(u32*)(dh + off) = hi;
            *(u32*)(dl + off) = lo;
        }
    }
}

// ---------------- attention: 128 queries/CTA, 64-key chunks ------------------
#define ATT_QBUF (256*PAD)
#define ATT_KVBUF (256*PAD)
#define ATT_SMEM ((ATT_QBUF + 2*ATT_KVBUF)*2)
__global__ __launch_bounds__(256) void attn_h(const float* __restrict__ mask){
    extern __shared__ __nv_bfloat16 sm[];
    __nv_bfloat16 *Qh = sm, *Ql = sm + 128*PAD;
    const int t = threadIdx.x, lane = t & 31, w = t >> 5;
    const int wn = w & 3, wm = w >> 2;      // 4(n) x 2(m); warp 32n x 32m
    const int n0 = blockIdx.x*128, k = blockIdx.y, b = blockIdx.z;
    const size_t bk = (size_t)(b*NH + k);

    // load Q tiles once (async, same group as first KV tile)
    for (int i = t; i < 2048; i += 256){
        int arr = i >> 10, idx = i & 1023, r = idx >> 3, c8 = (idx & 7)*8;
        const __nv_bfloat16* src = (arr ? g_Qpl : g_Qph) + (bk*NTOK + n0 + r)*DH + c8;
        CPA(sptr((arr ? Ql : Qh) + r*PAD + c8), src);
    }

    auto issueKV = [&](int mc, int pb){
        __nv_bfloat16* base = sm + ATT_QBUF + pb*ATT_KVBUF;
        for (int i = t; i < 2048; i += 256){
            int arr = i >> 9, idx = i & 511, r = idx >> 3, c8 = (idx & 7)*8;
            const __nv_bfloat16* src =
                ((arr == 0) ? g_Kph : (arr == 1) ? g_Kpl : (arr == 2) ? g_Vph : g_Vpl)
                + (bk*NTOK + mc + r)*DH + c8;
            CPA(sptr(base + arr*64*PAD + r*PAD + c8), src);
        }
        CPC();
    };

    const float* mp[4]; float rsum[4];
#pragma unroll
    for (int j = 0; j < 4; j++){
        int nl = wn*32 + (j >> 1)*16 + (lane >> 2) + (j & 1)*8;
        mp[j] = mask + n0 + nl;
        rsum[j] = 0.f;
    }
    float Oacc[2][8][4];
#pragma unroll
    for (int i=0;i<2;i++)
#pragma unroll
    for (int j=0;j<8;j++)
#pragma unroll
    for (int e=0;e<4;e++) Oacc[i][j][e]=0.f;

    const int arow = lane & 15, acolh = (lane >> 4) << 3;
    const int brow = (lane & 7) + ((lane & 16) >> 1), bcolh = lane & 8;
    const int vrow = (lane & 7) + (lane & 8), vcolh = (lane & 16) >> 1;

    issueKV(0, 0);
    for (int it = 0; it < NTOK/64; it++){
        const int mc = it*64;
        CPW0(); __syncthreads();
        if (it + 1 < NTOK/64) issueKV(mc + 64, (it + 1) & 1);
        __nv_bfloat16* base = sm + ATT_QBUF + (it & 1)*ATT_KVBUF;
        __nv_bfloat16 *Kh = base, *Kl = base + 64*PAD,
                      *Vh = base + 128*PAD, *Vl = base + 192*PAD;

        float S[2][4][4];
#pragma unroll
        for (int i=0;i<2;i++)
#pragma unroll
        for (int j=0;j<4;j++)
#pragma unroll
        for (int e=0;e<4;e++) S[i][j][e]=0.f;
#pragma unroll
        for (int ks = 0; ks < 4; ks++){
            u32 qh[2][4], ql2[2][4], kh2[2][4], kl2[2][4];
#pragma unroll
            for (int nt = 0; nt < 2; nt++){
                int ro = (wn*32 + nt*16 + arow)*PAD + ks*16 + acolh;
                ldsm4(qh[nt],  sptr(Qh + ro));
                ldsm4(ql2[nt], sptr(Ql + ro));
            }
#pragma unroll
            for (int p = 0; p < 2; p++){
                int ro = (wm*32 + p*16 + brow)*PAD + ks*16 + bcolh;
                ldsm4(kh2[p], sptr(Kh + ro));
                ldsm4(kl2[p], sptr(Kl + ro));
            }
#pragma unroll
            for (int nt = 0; nt < 2; nt++)
#pragma unroll
            for (int p = 0; p < 2; p++){
                mma16816(S[nt][2*p],   qh[nt],  &kh2[p][0]);
                mma16816(S[nt][2*p+1], qh[nt],  &kh2[p][2]);
                mma16816(S[nt][2*p],   qh[nt],  &kl2[p][0]);
                mma16816(S[nt][2*p+1], qh[nt],  &kl2[p][2]);
                mma16816(S[nt][2*p],   ql2[nt], &kh2[p][0]);
                mma16816(S[nt][2*p+1], ql2[nt], &kh2[p][2]);
            }
        }
        // softmax (logits are small; no max subtraction) + pack P fragments
        u32 ph[2][2][4], pl2[2][2][4];
#pragma unroll
        for (int nt = 0; nt < 2; nt++){
#pragma unroll
            for (int mt = 0; mt < 4; mt++)
#pragma unroll
            for (int e = 0; e < 4; e++){
                int m = mc + wm*32 + mt*8 + 2*(lane & 3) + (e & 1);
                float mval = mp[nt*2 + (e >> 1)][(size_t)m * NTOK];
                float p = fexp2((S[nt][mt][e] + mval) * SM_SCALE);
                rsum[nt*2 + (e >> 1)] += p;
                S[nt][mt][e] = p;
            }
#pragma unroll
            for (int kp = 0; kp < 2; kp++){
                pack2(S[nt][2*kp][0],   S[nt][2*kp][1],   ph[nt][kp][0], pl2[nt][kp][0]);
                pack2(S[nt][2*kp][2],   S[nt][2*kp][3],   ph[nt][kp][1], pl2[nt][kp][1]);
                pack2(S[nt][2*kp+1][0], S[nt][2*kp+1][1], ph[nt][kp][2], pl2[nt][kp][2]);
                pack2(S[nt][2*kp+1][2], S[nt][2*kp+1][3], ph[nt][kp][3], pl2[nt][kp][3]);
            }
        }
        // O += P @ V
#pragma unroll
        for (int kp = 0; kp < 2; kp++){
            u32 vh2[4][4], vl2[4][4];
#pragma unroll
            for (int pd = 0; pd < 4; pd++){
                int ro = (wm*32 + kp*16 + vrow)*PAD + pd*16 + vcolh;
                ldsm4t(vh2[pd], sptr(Vh + ro));
                ldsm4t(vl2[pd], sptr(Vl + ro));
            }
#pragma unroll
            for (int nt = 0; nt < 2; nt++)
#pragma unroll
            for (int pd = 0; pd < 4; pd++){
                mma16816(Oacc[nt][2*pd],   ph[nt][kp],  &vh2[pd][0]);
                mma16816(Oacc[nt][2*pd+1], ph[nt][kp],  &vh2[pd][2]);
                mma16816(Oacc[nt][2*pd],   ph[nt][kp],  &vl2[pd][0]);
                mma16816(Oacc[nt][2*pd+1], ph[nt][kp],  &vl2[pd][2]);
                mma16816(Oacc[nt][2*pd],   pl2[nt][kp], &vh2[pd][0]);
                mma16816(Oacc[nt][2*pd+1], pl2[nt][kp], &vh2[pd][2]);
            }
        }
    }
    // epilogue: cross-warp (wm) reduce + rowsum normalize + split store
    __syncthreads();
    float* Osm  = (float*)sm;          // [128][65]
    float* rssm = Osm + 128*65;        // [128][8]
#pragma unroll
    for (int j = 0; j < 4; j++){
        int nl = wn*32 + (j >> 1)*16 + (lane >> 2) + (j & 1)*8;
        rssm[nl*8 + wm*4 + (lane & 3)] = rsum[j];
    }
    if (wm == 1){
#pragma unroll
        for (int nt = 0; nt < 2; nt++)
#pragma unroll
        for (int dt = 0; dt < 8; dt++)
#pragma unroll
        for (int e = 0; e < 4; e++){
            int nl = wn*32 + nt*16 + (lane >> 2) + (e >> 1)*8;
            int d  = dt*8 + 2*(lane & 3) + (e & 1);
            Osm[nl*65 + d] = Oacc[nt][dt][e];
        }
    }
    __syncthreads();
    if (wm == 0){
        float inv[4];
#pragma unroll
        for (int j = 0; j < 4; j++){
            int nl = wn*32 + (j >> 1)*16 + (lane >> 2) + (j & 1)*8;
            float s = 0.f;
#pragma unroll
            for (int q = 0; q < 8; q++) s += rssm[nl*8 + q];
            inv[j] = 1.0f / s;
        }
#pragma unroll
        for (int nt = 0; nt < 2; nt++)
#pragma unroll
        for (int dt = 0; dt < 8; dt++)
#pragma unroll
        for (int h = 0; h < 2; h++){
            int nl = wn*32 + nt*16 + (lane >> 2) + h*8;
            int d  = dt*8 + 2*(lane & 3);
            float iv = inv[nt*2 + h];
            float v0 = (Oacc[nt][dt][h*2]   + Osm[nl*65 + d])     * iv;
            float v1 = (Oacc[nt][dt][h*2+1] + Osm[nl*65 + d + 1]) * iv;
            u32 hi, lo; pack2(v0, v1, hi, lo);
            size_t off = ((size_t)(b*NTOK + n0 + nl))*KD + (size_t)k*DH + d;
            *(u32*)(g_Ohh + off) = hi;
            *(u32*)(g_Oll + off) = lo;
        }
    }
}

// ---------------- output GEMM: out[128 x 128] = O[128 x 1024] @ W2^T ---------
#define OUT_BUF (512*PAD)
#define OUT_SMEM (2*OUT_BUF*2)
__global__ __launch_bounds__(256) void out_h(float* __restrict__ out){
    extern __shared__ __nv_bfloat16 sm[];
    const int t = threadIdx.x, lane = t & 31, w = t >> 5;
    const int wm = w & 1, wn = w >> 1;      // 2 x 4; warp 64m x 32n
    const int q0 = blockIdx.x*128, r0 = blockIdx.y*128;

    float acc[4][4][4];
#pragma unroll
    for (int i=0;i<4;i++)
#pragma unroll
    for (int j=0;j<4;j++)
#pragma unroll
    for (int e=0;e<4;e++) acc[i][j][e]=0.f;

    const int arow = lane & 15, acolh = (lane >> 4) << 3;
    const int brow = (lane & 7) + ((lane & 16) >> 1), bcolh = lane & 8;

    auto issue = [&](int kc, int pb){
        __nv_bfloat16* base = sm + pb*OUT_BUF;
        for (int i = t; i < 2048; i += 256){
            int arr = i >> 10, idx = i & 1023, r = idx >> 3, c8 = (idx & 7)*8;
            const __nv_bfloat16* src = (arr ? g_Oll : g_Ohh) + (size_t)(r0 + r)*KD + kc + c8;
            CPA(sptr(base + arr*128*PAD + r*PAD + c8), src);
        }
        for (int i = t; i < 2048; i += 256){
            int arr = i >> 10, idx = i & 1023, r = idx >> 3, c8 = (idx & 7)*8;
            const __nv_bfloat16* src = (arr ? g_W2l : g_W2h) + (size_t)(q0 + r)*KD + kc + c8;
            CPA(sptr(base + 256*PAD + arr*128*PAD + r*PAD + c8), src);
        }
        CPC();
    };

    issue(0, 0);
    for (int it = 0; it < 16; it++){
        CPW0(); __syncthreads();
        if (it + 1 < 16) issue((it + 1)*64, (it + 1) & 1);
        __nv_bfloat16* base = sm + (it & 1)*OUT_BUF;
        __nv_bfloat16 *Ah = base, *Al = base + 128*PAD,
                      *Bh = base + 256*PAD, *Bl = base + 384*PAD;
#pragma unroll
        for (int ks = 0; ks < 4; ks++){
            u32 ah[4][4], al2[4][4], bh[2][4], bl2[2][4];
#pragma unroll
            for (int mt = 0; mt < 4; mt++){
                int ro = (wm*64 + mt*16 + arow)*PAD + ks*16 + acolh;
                ldsm4(ah[mt],  sptr(Ah + ro));
                ldsm4(al2[mt], sptr(Al + ro));
            }
#pragma unroll
            for (int p = 0; p < 2; p++){
                int ro = (wn*32 + p*16 + brow)*PAD + ks*16 + bcolh;
                ldsm4(bh[p],  sptr(Bh + ro));
                ldsm4(bl2[p], sptr(Bl + ro));
            }
#pragma unroll
            for (int mt = 0; mt < 4; mt++)
#pragma unroll
            for (int p = 0; p < 2; p++){
                mma16816(acc[mt][2*p],   ah[mt],  &bh[p][0]);
                mma16816(acc[mt][2*p+1], ah[mt],  &bh[p][2]);
                mma16816(acc[mt][2*p],   ah[mt],  &bl2[p][0]);
                mma16816(acc[mt][2*p+1], ah[mt],  &bl2[p][2]);
                mma16816(acc[mt][2*p],   al2[mt], &bh[p][0]);
                mma16816(acc[mt][2*p+1], al2[mt], &bh[p][2]);
            }
        }
    }
#pragma unroll
    for (int mt = 0; mt < 4; mt++)
#pragma unroll
    for (int nt = 0; nt < 4; nt++)
#pragma unroll
    for (int h = 0; h < 2; h++){
        int r = r0 + wm*64 + mt*16 + (lane >> 2) + h*8;
        int c = q0 + wn*32 + nt*8 + 2*(lane & 3);
        *(float2*)(out + (size_t)r*CDIM + c) =
            make_float2(acc[mt][nt][h*2], acc[mt][nt][h*2+1]);
    }
}

// -----------------------------------------------------------------------------
extern "C" void kernel_launch(void* const* d_in, const int* in_sizes, int n_in,
                              void* d_out, int out_size)
{
    (void)in_sizes; (void)n_in; (void)out_size;
    const float* y    = (const float*)d_in[0];
    const float* mask = (const float*)d_in[1];
    const float* Lx   = (const float*)d_in[2];
    const float* Ly   = (const float*)d_in[3];
    const float* Tx   = (const float*)d_in[4];
    const float* Ty   = (const float*)d_in[5];
    float* out = (float*)d_out;

    cudaFuncSetAttribute(proj_h, cudaFuncAttributeMaxDynamicSharedMemorySize, PROJ_SMEM);
    cudaFuncSetAttribute(attn_h, cudaFuncAttributeMaxDynamicSharedMemorySize, ATT_SMEM);
    cudaFuncSetAttribute(out_h,  cudaFuncAttributeMaxDynamicSharedMemorySize, OUT_SMEM);

    split_y_k<<<4096, 256>>>(y);
    wcat_k<<<dim3(32, 2, 48), dim3(32, 8)>>>(Lx, Ly, Tx);
    wout_k<<<1024, 256>>>(Ty);
    proj_h<<<dim3(NTOK/128, NH, BB), 256, PROJ_SMEM>>>();
    attn_h<<<dim3(NTOK/128, NH, BB), 256, ATT_SMEM>>>(mask);
    out_h<<<dim3(CDIM/128, (BB*NTOK)/128), 256, OUT_SMEM>>>(out);
}

// round 6
// speedup vs baseline: 2.8214x; 1.0524x over previous
#include <cuda_runtime.h>
#include <cuda_bf16.h>

typedef unsigned int u32; typedef unsigned short u16;

#define BB 2
#define NTOK 2048
#define CDIM 1024
#define NH 16
#define DH 64
#define KD 1024
#define SM_SCALE 0.18033688011112042f  // log2(e)/sqrt(64)
#define PAD 72
#define MSTR 132

// scratch (static device arrays)
__device__ __nv_bfloat16 g_Yh[(size_t)BB*NTOK*CDIM];
__device__ __nv_bfloat16 g_Yl[(size_t)BB*NTOK*CDIM];
__device__ __nv_bfloat16 g_Wch[(size_t)NH*192*CDIM];   // [k][w*64+d][c]
__device__ __nv_bfloat16 g_Wcl[(size_t)NH*192*CDIM];
__device__ __nv_bfloat16 g_Kph[(size_t)BB*NH*NTOK*DH]; // [bk][m][d]
__device__ __nv_bfloat16 g_Kpl[(size_t)BB*NH*NTOK*DH];
__device__ __nv_bfloat16 g_Qph[(size_t)BB*NH*NTOK*DH];
__device__ __nv_bfloat16 g_Qpl[(size_t)BB*NH*NTOK*DH];
__device__ __nv_bfloat16 g_Vph[(size_t)BB*NH*NTOK*DH];
__device__ __nv_bfloat16 g_Vpl[(size_t)BB*NH*NTOK*DH];
__device__ __nv_bfloat16 g_Ohh[(size_t)BB*NTOK*KD];    // [bn][k*64+d]
__device__ __nv_bfloat16 g_Oll[(size_t)BB*NTOK*KD];
__device__ __nv_bfloat16 g_W2h[(size_t)CDIM*KD];       // [q][k*64+d]
__device__ __nv_bfloat16 g_W2l[(size_t)CDIM*KD];

// ---------------- helpers ----------------------------------------------------
__device__ __forceinline__ u32 sptr(const void* p){
    u32 a; asm("{ .reg .u64 t; cvta.to.shared.u64 t, %1; cvt.u32.u64 %0, t; }" : "=r"(a) : "l"(p)); return a;
}
#define CPA(dst, src) asm volatile("cp.async.cg.shared.global [%0], [%1], 16;" :: "r"(dst), "l"(src))
#define CPC()  asm volatile("cp.async.commit_group;" ::: "memory")
#define CPW0() asm volatile("cp.async.wait_group 0;" ::: "memory")

__device__ __forceinline__ void split1(float v, u16& h, u16& l){
    __nv_bfloat16 hb = __float2bfloat16(v);
    __nv_bfloat16 lb = __float2bfloat16(v - __bfloat162float(hb));
    h = __bfloat16_as_ushort(hb); l = __bfloat16_as_ushort(lb);
}
__device__ __forceinline__ void pack2(float x, float y, u32& hi, u32& lo){
    u16 hx,lx,hy,ly; split1(x,hx,lx); split1(y,hy,ly);
    hi = (u32)hx | ((u32)hy << 16); lo = (u32)lx | ((u32)ly << 16);
}
__device__ __forceinline__ float fexp2(float x){
    float y; asm("ex2.approx.ftz.f32 %0, %1;" : "=f"(y) : "f"(x)); return y;
}
__device__ __forceinline__ void mma16816(float* c, const u32* a, const u32* b){
    asm volatile("mma.sync.aligned.m16n8k16.row.col.f32.bf16.bf16.f32 "
        "{%0,%1,%2,%3}, {%4,%5,%6,%7}, {%8,%9}, {%0,%1,%2,%3};"
        : "+f"(c[0]), "+f"(c[1]), "+f"(c[2]), "+f"(c[3])
        : "r"(a[0]), "r"(a[1]), "r"(a[2]), "r"(a[3]), "r"(b[0]), "r"(b[1]));
}
__device__ __forceinline__ void ldsm4(u32* r, u32 a){
    asm volatile("ldmatrix.sync.aligned.m8n8.x4.shared.b16 {%0,%1,%2,%3}, [%4];"
        : "=r"(r[0]), "=r"(r[1]), "=r"(r[2]), "=r"(r[3]) : "r"(a));
}
__device__ __forceinline__ void ldsm4t(u32* r, u32 a){
    asm volatile("ldmatrix.sync.aligned.m8n8.x4.trans.shared.b16 {%0,%1,%2,%3}, [%4];"
        : "=r"(r[0]), "=r"(r[1]), "=r"(r[2]), "=r"(r[3]) : "r"(a));
}

// ---------------- prep kernels ------------------------------------------------
__global__ __launch_bounds__(256) void split_y_k(const float* __restrict__ y){
    size_t i = ((size_t)blockIdx.x*256 + threadIdx.x) * 4;
    float4 v = *(const float4*)(y + i);
    u32 h01,l01,h23,l23;
    pack2(v.x, v.y, h01, l01); pack2(v.z, v.w, h23, l23);
    *(uint2*)(g_Yh + i) = make_uint2(h01, h23);
    *(uint2*)(g_Yl + i) = make_uint2(l01, l23);
}
__global__ __launch_bounds__(256) void wcat_k(const float* __restrict__ Lx,
        const float* __restrict__ Ly, const float* __restrict__ Tx){
    __shared__ float t[32][33];
    int k = blockIdx.z / 3, w = blockIdx.z % 3;
    const float* src = (w == 0) ? Lx : ((w == 1) ? Ly : Tx);
    int c0 = blockIdx.x * 32, d0 = blockIdx.y * 32;
    int tx = threadIdx.x, ty = threadIdx.y;
#pragma unroll
    for (int s = 0; s < 4; s++)
        t[ty + 8*s][tx] = src[((size_t)k*CDIM + c0 + ty + 8*s)*DH + d0 + tx];
    __syncthreads();
#pragma unroll
    for (int s = 0; s < 4; s++){
        int r = ty + 8*s;
        u16 h,l; split1(t[tx][r], h, l);
        size_t o = ((size_t)k*192 + w*64 + d0 + r)*CDIM + c0 + tx;
        g_Wch[o] = __ushort_as_bfloat16(h);
        g_Wcl[o] = __ushort_as_bfloat16(l);
    }
}
__global__ __launch_bounds__(256) void wout_k(const float* __restrict__ Ty){
    size_t i = ((size_t)blockIdx.x*256 + threadIdx.x) * 4;
    int k = (int)(i >> 16), q = (int)((i >> 6) & 1023), d = (int)(i & 63);
    float4 v = *(const float4*)(Ty + i);
    u32 h01,l01,h23,l23;
    pack2(v.x, v.y, h01, l01); pack2(v.z, v.w, h23, l23);
    size_t o = (size_t)q*KD + (size_t)k*64 + d;
    *(uint2*)(g_W2h + o) = make_uint2(h01, h23);
    *(uint2*)(g_W2l + o) = make_uint2(l01, l23);
}

// ---------------- projection: D[128 x 192] = Y[128 x 1024] @ Wcat^T ----------
// 512 threads, 16 warps as 4(m) x 4(n); warp tile 32m x 48n
#define PROJ_BUF (640*PAD)
#define PROJ_SMEM (2*PROJ_BUF*2)
__global__ __launch_bounds__(512) void proj_h(){
    extern __shared__ __nv_bfloat16 sm[];
    const int t = threadIdx.x, lane = t & 31, w = t >> 5;
    const int wm = w & 3, wn = w >> 2;
    const int m0 = blockIdx.x*128, k = blockIdx.y, b = blockIdx.z;
    const size_t bk = (size_t)(b*NH + k);
    const __nv_bfloat16 *Ygh = g_Yh + (size_t)(b*NTOK + m0)*CDIM;
    const __nv_bfloat16 *Ygl = g_Yl + (size_t)(b*NTOK + m0)*CDIM;
    const __nv_bfloat16 *Wgh = g_Wch + (size_t)k*192*CDIM;
    const __nv_bfloat16 *Wgl = g_Wcl + (size_t)k*192*CDIM;

    float acc[2][6][4];
#pragma unroll
    for (int i=0;i<2;i++)
#pragma unroll
    for (int j=0;j<6;j++)
#pragma unroll
    for (int e=0;e<4;e++) acc[i][j][e]=0.f;

    const int arow = lane & 15, acolh = (lane >> 4) << 3;
    const int brow = (lane & 7) + ((lane & 16) >> 1), bcolh = lane & 8;

    auto issue = [&](int kc, int pb){
        __nv_bfloat16* base = sm + pb*PROJ_BUF;
        for (int i = t; i < 2048; i += 512){
            int arr = i >> 10, idx = i & 1023, r = idx >> 3, c8 = (idx & 7)*8;
            const __nv_bfloat16* src = (arr ? Ygl : Ygh) + (size_t)r*CDIM + kc + c8;
            CPA(sptr(base + arr*128*PAD + r*PAD + c8), src);
        }
        for (int i = t; i < 3072; i += 512){
            int arr = i >= 1536, idx = arr ? i - 1536 : i, r = idx >> 3, c8 = (idx & 7)*8;
            const __nv_bfloat16* src = (arr ? Wgl : Wgh) + (size_t)r*CDIM + kc + c8;
            CPA(sptr(base + 256*PAD + arr*192*PAD + r*PAD + c8), src);
        }
        CPC();
    };

    issue(0, 0);
    for (int it = 0; it < 16; it++){
        CPW0(); __syncthreads();
        if (it + 1 < 16) issue((it + 1)*64, (it + 1) & 1);
        __nv_bfloat16* base = sm + (it & 1)*PROJ_BUF;
        __nv_bfloat16 *Ah = base, *Al = base + 128*PAD,
                      *Bh = base + 256*PAD, *Bl = base + 448*PAD;
#pragma unroll
        for (int ks = 0; ks < 4; ks++){
            u32 ah[2][4], al2[2][4], bh[3][4], bl2[3][4];
#pragma unroll
            for (int mt = 0; mt < 2; mt++){
                int ro = (wm*32 + mt*16 + arow)*PAD + ks*16 + acolh;
                ldsm4(ah[mt],  sptr(Ah + ro));
                ldsm4(al2[mt], sptr(Al + ro));
            }
#pragma unroll
            for (int p = 0; p < 3; p++){
                int ro = (wn*48 + p*16 + brow)*PAD + ks*16 + bcolh;
                ldsm4(bh[p],  sptr(Bh + ro));
                ldsm4(bl2[p], sptr(Bl + ro));
            }
#pragma unroll
            for (int mt = 0; mt < 2; mt++)
#pragma unroll
            for (int p = 0; p < 3; p++){
                mma16816(acc[mt][2*p],   ah[mt],  &bh[p][0]);
                mma16816(acc[mt][2*p+1], ah[mt],  &bh[p][2]);
                mma16816(acc[mt][2*p],   ah[mt],  &bl2[p][0]);
                mma16816(acc[mt][2*p+1], ah[mt],  &bl2[p][2]);
                mma16816(acc[mt][2*p],   al2[mt], &bh[p][0]);
                mma16816(acc[mt][2*p+1], al2[mt], &bh[p][2]);
            }
        }
    }
    // epilogue: split-store to K/Q/V (token-major [m][64])
#pragma unroll
    for (int mt = 0; mt < 2; mt++)
#pragma unroll
    for (int nt = 0; nt < 6; nt++){
        int cbase = wn*48 + nt*8 + 2*(lane & 3);
        int wsel = cbase >> 6, d = cbase & 63;
        __nv_bfloat16* dh = (wsel == 0) ? g_Kph : (wsel == 1) ? g_Qph : g_Vph;
        __nv_bfloat16* dl = (wsel == 0) ? g_Kpl : (wsel == 1) ? g_Qpl : g_Vpl;
#pragma unroll
        for (int h = 0; h < 2; h++){
            int m = m0 + wm*32 + mt*16 + (lane >> 2) + h*8;
            u32 hi, lo; pack2(acc[mt][nt][h*2], acc[mt][nt][h*2+1], hi, lo);
            size_t off = (bk*NTOK + m)*DH + d;
            *(u32*)(dh + off) = hi;
            *(u32*)(dl + off) = lo;
        }
    }
}

// ---------------- attention: 128 queries/CTA, 64-key chunks ------------------
#define ATT_QBUF (256*PAD)
#define ATT_KV (256*PAD)
#define ATT_BUFTOT (ATT_KV + 64*MSTR*2)     // KV bf16 + mask fp32 region (bf16 units)
#define ATT_SMEM ((ATT_QBUF + 2*ATT_BUFTOT)*2)
__global__ __launch_bounds__(256) void attn_h(const float* __restrict__ mask){
    extern __shared__ __nv_bfloat16 sm[];
    __nv_bfloat16 *Qh = sm, *Ql = sm + 128*PAD;
    const int t = threadIdx.x, lane = t & 31, w = t >> 5;
    const int wn = w & 3, wm = w >> 2;      // 4(n) x 2(m); warp 32n x 32m
    const int n0 = blockIdx.x*128, k = blockIdx.y, b = blockIdx.z;
    const size_t bk = (size_t)(b*NH + k);

    // load Q tiles once (async, same group as first KV tile)
    for (int i = t; i < 2048; i += 256){
        int arr = i >> 10, idx = i & 1023, r = idx >> 3, c8 = (idx & 7)*8;
        const __nv_bfloat16* src = (arr ? g_Qpl : g_Qph) + (bk*NTOK + n0 + r)*DH + c8;
        CPA(sptr((arr ? Ql : Qh) + r*PAD + c8), src);
    }

    auto issueKV = [&](int mc, int pb){
        __nv_bfloat16* base = sm + ATT_QBUF + pb*ATT_BUFTOT;
        for (int i = t; i < 2048; i += 256){
            int arr = i >> 9, idx = i & 511, r = idx >> 3, c8 = (idx & 7)*8;
            const __nv_bfloat16* src =
                ((arr == 0) ? g_Kph : (arr == 1) ? g_Kpl : (arr == 2) ? g_Vph : g_Vpl)
                + (bk*NTOK + mc + r)*DH + c8;
            CPA(sptr(base + arr*64*PAD + r*PAD + c8), src);
        }
        // mask tile [64 m][128 n] fp32, coalesced rows
        float* mdst = (float*)(base + ATT_KV);
        for (int i = t; i < 2048; i += 256){
            int r = i >> 5, c4 = (i & 31)*4;
            CPA(sptr(mdst + r*MSTR + c4), mask + (size_t)(mc + r)*NTOK + n0 + c4);
        }
        CPC();
    };

    float rsum[4];
#pragma unroll
    for (int j = 0; j < 4; j++) rsum[j] = 0.f;
    float Oacc[2][8][4];
#pragma unroll
    for (int i=0;i<2;i++)
#pragma unroll
    for (int j=0;j<8;j++)
#pragma unroll
    for (int e=0;e<4;e++) Oacc[i][j][e]=0.f;

    const int arow = lane & 15, acolh = (lane >> 4) << 3;
    const int brow = (lane & 7) + ((lane & 16) >> 1), bcolh = lane & 8;
    const int vrow = (lane & 7) + (lane & 8), vcolh = (lane & 16) >> 1;

    issueKV(0, 0);
    for (int it = 0; it < NTOK/64; it++){
        const int mc = it*64;
        CPW0(); __syncthreads();
        if (it + 1 < NTOK/64) issueKV(mc + 64, (it + 1) & 1);
        __nv_bfloat16* base = sm + ATT_QBUF + (it & 1)*ATT_BUFTOT;
        __nv_bfloat16 *Kh = base, *Kl = base + 64*PAD,
                      *Vh = base + 128*PAD, *Vl = base + 192*PAD;
        const float* msk = (const float*)(base + ATT_KV);

        float S[2][4][4];
#pragma unroll
        for (int i=0;i<2;i++)
#pragma unroll
        for (int j=0;j<4;j++)
#pragma unroll
        for (int e=0;e<4;e++) S[i][j][e]=0.f;
#pragma unroll
        for (int ks = 0; ks < 4; ks++){
            u32 qh[2][4], ql2[2][4], kh2[2][4], kl2[2][4];
#pragma unroll
            for (int nt = 0; nt < 2; nt++){
                int ro = (wn*32 + nt*16 + arow)*PAD + ks*16 + acolh;
                ldsm4(qh[nt],  sptr(Qh + ro));
                ldsm4(ql2[nt], sptr(Ql + ro));
            }
#pragma unroll
            for (int p = 0; p < 2; p++){
                int ro = (wm*32 + p*16 + brow)*PAD + ks*16 + bcolh;
                ldsm4(kh2[p], sptr(Kh + ro));
                ldsm4(kl2[p], sptr(Kl + ro));
            }
#pragma unroll
            for (int nt = 0; nt < 2; nt++)
#pragma unroll
            for (int p = 0; p < 2; p++){
                mma16816(S[nt][2*p],   qh[nt],  &kh2[p][0]);
                mma16816(S[nt][2*p+1], qh[nt],  &kh2[p][2]);
                mma16816(S[nt][2*p],   qh[nt],  &kl2[p][0]);
                mma16816(S[nt][2*p+1], qh[nt],  &kl2[p][2]);
                mma16816(S[nt][2*p],   ql2[nt], &kh2[p][0]);
                mma16816(S[nt][2*p+1], ql2[nt], &kh2[p][2]);
            }
        }
        // softmax (logits small; no max subtraction) + pack P fragments
        u32 ph[2][2][4], pl2[2][2][4];
#pragma unroll
        for (int nt = 0; nt < 2; nt++){
#pragma unroll
            for (int mt = 0; mt < 4; mt++)
#pragma unroll
            for (int e = 0; e < 4; e++){
                int ml = wm*32 + mt*8 + 2*(lane & 3) + (e & 1);
                int nl = wn*32 + nt*16 + (lane >> 2) + (e >> 1)*8;
                float p = fexp2((S[nt][mt][e] + msk[ml*MSTR + nl]) * SM_SCALE);
                rsum[nt*2 + (e >> 1)] += p;
                S[nt][mt][e] = p;
            }
#pragma unroll
            for (int kp = 0; kp < 2; kp++){
                pack2(S[nt][2*kp][0],   S[nt][2*kp][1],   ph[nt][kp][0], pl2[nt][kp][0]);
                pack2(S[nt][2*kp][2],   S[nt][2*kp][3],   ph[nt][kp][1], pl2[nt][kp][1]);
                pack2(S[nt][2*kp+1][0], S[nt][2*kp+1][1], ph[nt][kp][2], pl2[nt][kp][2]);
                pack2(S[nt][2*kp+1][2], S[nt][2*kp+1][3], ph[nt][kp][3], pl2[nt][kp][3]);
            }
        }
        // O += P @ V
#pragma unroll
        for (int kp = 0; kp < 2; kp++){
            u32 vh2[4][4], vl2[4][4];
#pragma unroll
            for (int pd = 0; pd < 4; pd++){
                int ro = (wm*32 + kp*16 + vrow)*PAD + pd*16 + vcolh;
                ldsm4t(vh2[pd], sptr(Vh + ro));
                ldsm4t(vl2[pd], sptr(Vl + ro));
            }
#pragma unroll
            for (int nt = 0; nt < 2; nt++)
#pragma unroll
            for (int pd = 0; pd < 4; pd++){
                mma16816(Oacc[nt][2*pd],   ph[nt][kp],  &vh2[pd][0]);
                mma16816(Oacc[nt][2*pd+1], ph[nt][kp],  &vh2[pd][2]);
                mma16816(Oacc[nt][2*pd],   ph[nt][kp],  &vl2[pd][0]);
                mma16816(Oacc[nt][2*pd+1], ph[nt][kp],  &vl2[pd][2]);
                mma16816(Oacc[nt][2*pd],   pl2[nt][kp], &vh2[pd][0]);
                mma16816(Oacc[nt][2*pd+1], pl2[nt][kp], &vh2[pd][2]);
            }
        }
    }
    // epilogue: cross-warp (wm) reduce + rowsum normalize + split store
    __syncthreads();
    float* Osm  = (float*)sm;          // [128][65]
    float* rssm = Osm + 128*65;        // [128][8]
#pragma unroll
    for (int j = 0; j < 4; j++){
        int nl = wn*32 + (j >> 1)*16 + (lane >> 2) + (j & 1)*8;
        rssm[nl*8 + wm*4 + (lane & 3)] = rsum[j];
    }
    if (wm == 1){
#pragma unroll
        for (int nt = 0; nt < 2; nt++)
#pragma unroll
        for (int dt = 0; dt < 8; dt++)
#pragma unroll
        for (int e = 0; e < 4; e++){
            int nl = wn*32 + nt*16 + (lane >> 2) + (e >> 1)*8;
            int d  = dt*8 + 2*(lane & 3) + (e & 1);
            Osm[nl*65 + d] = Oacc[nt][dt][e];
        }
    }
    __syncthreads();
    if (wm == 0){
        float inv[4];
#pragma unroll
        for (int j = 0; j < 4; j++){
            int nl = wn*32 + (j >> 1)*16 + (lane >> 2) + (j & 1)*8;
            float s = 0.f;
#pragma unroll
            for (int q = 0; q < 8; q++) s += rssm[nl*8 + q];
            inv[j] = 1.0f / s;
        }
#pragma unroll
        for (int nt = 0; nt < 2; nt++)
#pragma unroll
        for (int dt = 0; dt < 8; dt++)
#pragma unroll
        for (int h = 0; h < 2; h++){
            int nl = wn*32 + nt*16 + (lane >> 2) + h*8;
            int d  = dt*8 + 2*(lane & 3);
            float iv = inv[nt*2 + h];
            float v0 = (Oacc[nt][dt][h*2]   + Osm[nl*65 + d])     * iv;
            float v1 = (Oacc[nt][dt][h*2+1] + Osm[nl*65 + d + 1]) * iv;
            u32 hi, lo; pack2(v0, v1, hi, lo);
            size_t off = ((size_t)(b*NTOK + n0 + nl))*KD + (size_t)k*DH + d;
            *(u32*)(g_Ohh + off) = hi;
            *(u32*)(g_Oll + off) = lo;
        }
    }
}

// ---------------- output GEMM: out[128 x 128] = O[128 x 1024] @ W2^T ---------
// 512 threads, 16 warps as 4(m) x 4(n); warp tile 32m x 32n
#define OUT_BUF (512*PAD)
#define OUT_SMEM (2*OUT_BUF*2)
__global__ __launch_bounds__(512) void out_h(float* __restrict__ out){
    extern __shared__ __nv_bfloat16 sm[];
    const int t = threadIdx.x, lane = t & 31, w = t >> 5;
    const int wm = w & 3, wn = w >> 2;
    const int q0 = blockIdx.x*128, r0 = blockIdx.y*128;

    float acc[2][4][4];
#pragma unroll
    for (int i=0;i<2;i++)
#pragma unroll
    for (int j=0;j<4;j++)
#pragma unroll
    for (int e=0;e<4;e++) acc[i][j][e]=0.f;

    const int arow = lane & 15, acolh = (lane >> 4) << 3;
    const int brow = (lane & 7) + ((lane & 16) >> 1), bcolh = lane & 8;

    auto issue = [&](int kc, int pb){
        __nv_bfloat16* base = sm + pb*OUT_BUF;
        for (int i = t; i < 2048; i += 512){
            int arr = i >> 10, idx = i & 1023, r = idx >> 3, c8 = (idx & 7)*8;
            const __nv_bfloat16* src = (arr ? g_Oll : g_Ohh) + (size_t)(r0 + r)*KD + kc + c8;
            CPA(sptr(base + arr*128*PAD + r*PAD + c8), src);
        }
        for (int i = t; i < 2048; i += 512){
            int arr = i >> 10, idx = i & 1023, r = idx >> 3, c8 = (idx & 7)*8;
            const __nv_bfloat16* src = (arr ? g_W2l : g_W2h) + (size_t)(q0 + r)*KD + kc + c8;
            CPA(sptr(base + 256*PAD + arr*128*PAD + r*PAD + c8), src);
        }
        CPC();
    };

    issue(0, 0);
    for (int it = 0; it < 16; it++){
        CPW0(); __syncthreads();
        if (it + 1 < 16) issue((it + 1)*64, (it + 1) & 1);
        __nv_bfloat16* base = sm + (it & 1)*OUT_BUF;
        __nv_bfloat16 *Ah = base, *Al = base + 128*PAD,
                      *Bh = base + 256*PAD, *Bl = base + 384*PAD;
#pragma unroll
        for (int ks = 0; ks < 4; ks++){
            u32 ah[2][4], al2[2][4], bh[2][4], bl2[2][4];
#pragma unroll
            for (int mt = 0; mt < 2; mt++){
                int ro = (wm*32 + mt*16 + arow)*PAD + ks*16 + acolh;
                ldsm4(ah[mt],  sptr(Ah + ro));
                ldsm4(al2[mt], sptr(Al + ro));
            }
#pragma unroll
            for (int p = 0; p < 2; p++){
                int ro = (wn*32 + p*16 + brow)*PAD + ks*16 + bcolh;
                ldsm4(bh[p],  sptr(Bh + ro));
                ldsm4(bl2[p], sptr(Bl + ro));
            }
#pragma unroll
            for (int mt = 0; mt < 2; mt++)
#pragma unroll
            for (int p = 0; p < 2; p++){
                mma16816(acc[mt][2*p],   ah[mt],  &bh[p][0]);
                mma16816(acc[mt][2*p+1], ah[mt],  &bh[p][2]);
                mma16816(acc[mt][2*p],   ah[mt],  &bl2[p][0]);
                mma16816(acc[mt][2*p+1], ah[mt],  &bl2[p][2]);
                mma16816(acc[mt][2*p],   al2[mt], &bh[p][0]);
                mma16816(acc[mt][2*p+1], al2[mt], &bh[p][2]);
            }
        }
    }
#pragma unroll
    for (int mt = 0; mt < 2; mt++)
#pragma unroll
    for (int nt = 0; nt < 4; nt++)
#pragma unroll
    for (int h = 0; h < 2; h++){
        int r = r0 + wm*32 + mt*16 + (lane >> 2) + h*8;
        int c = q0 + wn*32 + nt*8 + 2*(lane & 3);
        *(float2*)(out + (size_t)r*CDIM + c) =
            make_float2(acc[mt][nt][h*2], acc[mt][nt][h*2+1]);
    }
}

// -----------------------------------------------------------------------------
extern "C" void kernel_launch(void* const* d_in, const int* in_sizes, int n_in,
                              void* d_out, int out_size)
{
    (void)in_sizes; (void)n_in; (void)out_size;
    const float* y    = (const float*)d_in[0];
    const float* mask = (const float*)d_in[1];
    const float* Lx   = (const float*)d_in[2];
    const float* Ly   = (const float*)d_in[3];
    const float* Tx   = (const float*)d_in[4];
    const float* Ty   = (const float*)d_in[5];
    float* out = (float*)d_out;

    cudaFuncSetAttribute(proj_h, cudaFuncAttributeMaxDynamicSharedMemorySize, PROJ_SMEM);
    cudaFuncSetAttribute(attn_h, cudaFuncAttributeMaxDynamicSharedMemorySize, ATT_SMEM);
    cudaFuncSetAttribute(out_h,  cudaFuncAttributeMaxDynamicSharedMemorySize, OUT_SMEM);

    split_y_k<<<4096, 256>>>(y);
    wcat_k<<<dim3(32, 2, 48), dim3(32, 8)>>>(Lx, Ly, Tx);
    wout_k<<<1024, 256>>>(Ty);
    proj_h<<<dim3(NTOK/128, NH, BB), 512, PROJ_SMEM>>>();
    attn_h<<<dim3(NTOK/128, NH, BB), 256, ATT_SMEM>>>(mask);
    out_h<<<dim3(CDIM/128, (BB*NTOK)/128), 512, OUT_SMEM>>>(out);
}

// round 8
// speedup vs baseline: 2.9996x; 1.0632x over previous
#include <cuda_runtime.h>
#include <cuda_bf16.h>

typedef unsigned int u32; typedef unsigned short u16; typedef unsigned long long u64;

#define BB 2
#define NTOK 2048
#define CDIM 1024
#define NH 16
#define DH 64
#define KD 1024
#define SM_SCALE 0.18033688011112042f  // log2(e)/sqrt(64)
#define PAD 72
#define MSTR 132

// scratch (static device arrays)
__device__ __nv_bfloat16 g_Yh[(size_t)BB*NTOK*CDIM];
__device__ __nv_bfloat16 g_Yl[(size_t)BB*NTOK*CDIM];
__device__ __nv_bfloat16 g_Wch[(size_t)NH*192*CDIM];   // [k][w*64+d][c]
__device__ __nv_bfloat16 g_Wcl[(size_t)NH*192*CDIM];
__device__ __nv_bfloat16 g_Kph[(size_t)BB*NH*NTOK*DH]; // [bk][m][d]
__device__ __nv_bfloat16 g_Kpl[(size_t)BB*NH*NTOK*DH];
__device__ __nv_bfloat16 g_Qph[(size_t)BB*NH*NTOK*DH];
__device__ __nv_bfloat16 g_Qpl[(size_t)BB*NH*NTOK*DH];
__device__ __nv_bfloat16 g_Vph[(size_t)BB*NH*NTOK*DH];
__device__ __nv_bfloat16 g_Vpl[(size_t)BB*NH*NTOK*DH];
__device__ __nv_bfloat16 g_Ohh[(size_t)BB*NTOK*KD];    // [bn][k*64+d]
__device__ __nv_bfloat16 g_Oll[(size_t)BB*NTOK*KD];
__device__ __nv_bfloat16 g_W2h[(size_t)CDIM*KD];       // [q][k*64+d]
__device__ __nv_bfloat16 g_W2l[(size_t)CDIM*KD];

// ---------------- helpers ----------------------------------------------------
__device__ __forceinline__ u32 sptr(const void* p){
    u32 a; asm("{ .reg .u64 t; cvta.to.shared.u64 t, %1; cvt.u32.u64 %0, t; }" : "=r"(a) : "l"(p)); return a;
}
#define CPA(dst, src) asm volatile("cp.async.cg.shared.global [%0], [%1], 16;" :: "r"(dst), "l"(src))
#define CPC()  asm volatile("cp.async.commit_group;" ::: "memory")
#define CPW0() asm volatile("cp.async.wait_group 0;" ::: "memory")

__device__ __forceinline__ void split1(float v, u16& h, u16& l){
    __nv_bfloat16 hb = __float2bfloat16(v);
    __nv_bfloat16 lb = __float2bfloat16(v - __bfloat162float(hb));
    h = __bfloat16_as_ushort(hb); l = __bfloat16_as_ushort(lb);
}
__device__ __forceinline__ void pack2(float x, float y, u32& hi, u32& lo){
    u16 hx,lx,hy,ly; split1(x,hx,lx); split1(y,hy,ly);
    hi = (u32)hx | ((u32)hy << 16); lo = (u32)lx | ((u32)ly << 16);
}
__device__ __forceinline__ float fexp2(float x){
    float y; asm("ex2.approx.ftz.f32 %0, %1;" : "=f"(y) : "f"(x)); return y;
}
__device__ __forceinline__ void mma16816(float* c, const u32* a, const u32* b){
    asm volatile("mma.sync.aligned.m16n8k16.row.col.f32.bf16.bf16.f32 "
        "{%0,%1,%2,%3}, {%4,%5,%6,%7}, {%8,%9}, {%0,%1,%2,%3};"
        : "+f"(c[0]), "+f"(c[1]), "+f"(c[2]), "+f"(c[3])
        : "r"(a[0]), "r"(a[1]), "r"(a[2]), "r"(a[3]), "r"(b[0]), "r"(b[1]));
}
__device__ __forceinline__ void ldsm4(u32* r, u32 a){
    asm volatile("ldmatrix.sync.aligned.m8n8.x4.shared.b16 {%0,%1,%2,%3}, [%4];"
        : "=r"(r[0]), "=r"(r[1]), "=r"(r[2]), "=r"(r[3]) : "r"(a));
}
__device__ __forceinline__ void ldsm4t(u32* r, u32 a){
    asm volatile("ldmatrix.sync.aligned.m8n8.x4.trans.shared.b16 {%0,%1,%2,%3}, [%4];"
        : "=r"(r[0]), "=r"(r[1]), "=r"(r[2]), "=r"(r[3]) : "r"(a));
}

// ---------------- prep kernels ------------------------------------------------
__global__ __launch_bounds__(256) void split_y_k(const float* __restrict__ y){
    size_t i = ((size_t)blockIdx.x*256 + threadIdx.x) * 4;
    float4 v = *(const float4*)(y + i);
    u32 h01,l01,h23,l23;
    pack2(v.x, v.y, h01, l01); pack2(v.z, v.w, h23, l23);
    *(uint2*)(g_Yh + i) = make_uint2(h01, h23);
    *(uint2*)(g_Yl + i) = make_uint2(l01, l23);
}
__global__ __launch_bounds__(256) void wcat_k(const float* __restrict__ Lx,
        const float* __restrict__ Ly, const float* __restrict__ Tx){
    __shared__ float t[32][33];
    int k = blockIdx.z / 3, w = blockIdx.z % 3;
    const float* src = (w == 0) ? Lx : ((w == 1) ? Ly : Tx);
    int c0 = blockIdx.x * 32, d0 = blockIdx.y * 32;
    int tx = threadIdx.x, ty = threadIdx.y;
#pragma unroll
    for (int s = 0; s < 4; s++)
        t[ty + 8*s][tx] = src[((size_t)k*CDIM + c0 + ty + 8*s)*DH + d0 + tx];
    __syncthreads();
#pragma unroll
    for (int s = 0; s < 4; s++){
        int r = ty + 8*s;
        u16 h,l; split1(t[tx][r], h, l);
        size_t o = ((size_t)k*192 + w*64 + d0 + r)*CDIM + c0 + tx;
        g_Wch[o] = __ushort_as_bfloat16(h);
        g_Wcl[o] = __ushort_as_bfloat16(l);
    }
}
__global__ __launch_bounds__(256) void wout_k(const float* __restrict__ Ty){
    size_t i = ((size_t)blockIdx.x*256 + threadIdx.x) * 4;
    int k = (int)(i >> 16), q = (int)((i >> 6) & 1023), d = (int)(i & 63);
    float4 v = *(const float4*)(Ty + i);
    u32 h01,l01,h23,l23;
    pack2(v.x, v.y, h01, l01); pack2(v.z, v.w, h23, l23);
    size_t o = (size_t)q*KD + (size_t)k*64 + d;
    *(uint2*)(g_W2h + o) = make_uint2(h01, h23);
    *(uint2*)(g_W2l + o) = make_uint2(l01, l23);
}

// ---------------- projection: D[128 x 192] = Y[128 x 1024] @ Wcat^T ----------
// 512 threads, 16 warps as 4(m) x 4(n); warp tile 32m x 48n
#define PROJ_BUF (640*PAD)
#define PROJ_BUFB (PROJ_BUF*2)
#define PROJ_SMEM (2*PROJ_BUF*2)
__global__ __launch_bounds__(512) void proj_h(){
    extern __shared__ __nv_bfloat16 sm[];
    const int t = threadIdx.x, lane = t & 31, w = t >> 5;
    const int wm = w & 3, wn = w >> 2;
    const int m0 = blockIdx.x*128, k = blockIdx.y, b = blockIdx.z;
    const size_t bk = (size_t)(b*NH + k);
    const u32 sm0 = sptr(sm);

    // hoisted cp.async addressing (thread t -> row ar in [0,64), 8-col chunk)
    const int ar = t >> 3, ac8 = (t & 7)*8;
    const __nv_bfloat16* pYh = g_Yh + (size_t)(b*NTOK + m0 + ar)*CDIM + ac8;
    const __nv_bfloat16* pYl = g_Yl + (size_t)(b*NTOK + m0 + ar)*CDIM + ac8;
    const __nv_bfloat16* pWh = g_Wch + ((size_t)k*192 + ar)*CDIM + ac8;
    const __nv_bfloat16* pWl = g_Wcl + ((size_t)k*192 + ar)*CDIM + ac8;
    const u32 dA = sm0 + (u32)((ar*PAD + ac8)*2);
    const u32 dB = sm0 + (u32)((256*PAD + ar*PAD + ac8)*2);
    int koff = 0;

    float acc[2][6][4];
#pragma unroll
    for (int i=0;i<2;i++)
#pragma unroll
    for (int j=0;j<6;j++)
#pragma unroll
    for (int e=0;e<4;e++) acc[i][j][e]=0.f;

    const int arow = lane & 15, acolh = (lane >> 4) << 3;
    const int brow = (lane & 7) + ((lane & 16) >> 1), bcolh = lane & 8;
    const u32 aBase = sm0 + (u32)(((wm*32 + arow)*PAD + acolh)*2);
    const u32 bBase = sm0 + (u32)((256*PAD + (wn*48 + brow)*PAD + bcolh)*2);

    auto issue = [&](int pb){
        u32 da = dA + (u32)(pb*PROJ_BUFB);
        CPA(da,               pYh + koff);
        CPA(da + 64*PAD*2,    pYh + koff + 64*CDIM);
        CPA(da + 128*PAD*2,   pYl + koff);
        CPA(da + 192*PAD*2,   pYl + koff + 64*CDIM);
        u32 db = dB + (u32)(pb*PROJ_BUFB);
        CPA(db,               pWh + koff);
        CPA(db + 64*PAD*2,    pWh + koff + 64*CDIM);
        CPA(db + 128*PAD*2,   pWh + koff + 128*CDIM);
        CPA(db + 192*PAD*2,   pWl + koff);
        CPA(db + 256*PAD*2,   pWl + koff + 64*CDIM);
        CPA(db + 320*PAD*2,   pWl + koff + 128*CDIM);
        CPC();
        koff += 64;
    };

    issue(0);
    for (int it = 0; it < 16; it++){
        CPW0(); __syncthreads();
        if (it + 1 < 16) issue((it + 1) & 1);
        const u32 bs = (u32)((it & 1)*PROJ_BUFB);
#pragma unroll
        for (int ks = 0; ks < 4; ks++){
            u32 ah[2][4], al2[2][4], bh[3][4], bl2[3][4];
#pragma unroll
            for (int mt = 0; mt < 2; mt++){
                ldsm4(ah[mt],  aBase + bs + (u32)((mt*16*PAD + ks*16)*2));
                ldsm4(al2[mt], aBase + bs + (u32)(((128 + mt*16)*PAD + ks*16)*2));
            }
#pragma unroll
            for (int p = 0; p < 3; p++){
                ldsm4(bh[p],  bBase + bs + (u32)((p*16*PAD + ks*16)*2));
                ldsm4(bl2[p], bBase + bs + (u32)(((192 + p*16)*PAD + ks*16)*2));
            }
#pragma unroll
            for (int mt = 0; mt < 2; mt++)
#pragma unroll
            for (int p = 0; p < 3; p++){
                mma16816(acc[mt][2*p],   ah[mt],  &bh[p][0]);
                mma16816(acc[mt][2*p+1], ah[mt],  &bh[p][2]);
                mma16816(acc[mt][2*p],   ah[mt],  &bl2[p][0]);
                mma16816(acc[mt][2*p+1], ah[mt],  &bl2[p][2]);
                mma16816(acc[mt][2*p],   al2[mt], &bh[p][0]);
                mma16816(acc[mt][2*p+1], al2[mt], &bh[p][2]);
            }
        }
    }
    // epilogue: split-store to K/Q/V (token-major [m][64])
#pragma unroll
    for (int mt = 0; mt < 2; mt++)
#pragma unroll
    for (int nt = 0; nt < 6; nt++){
        int cbase = wn*48 + nt*8 + 2*(lane & 3);
        int wsel = cbase >> 6, d = cbase & 63;
        __nv_bfloat16* dh = (wsel == 0) ? g_Kph : (wsel == 1) ? g_Qph : g_Vph;
        __nv_bfloat16* dl = (wsel == 0) ? g_Kpl : (wsel == 1) ? g_Qpl : g_Vpl;
#pragma unroll
        for (int h = 0; h < 2; h++){
            int m = m0 + wm*32 + mt*16 + (lane >> 2) + h*8;
            u32 hi, lo; pack2(acc[mt][nt][h*2], acc[mt][nt][h*2+1], hi, lo);
            size_t off = (bk*NTOK + m)*DH + d;
            *(u32*)(dh + off) = hi;
            *(u32*)(dl + off) = lo;
        }
    }
}

// ---------------- attention: 128 queries/CTA, 64-key chunks ------------------
#define ATT_QBUF (256*PAD)
#define ATT_KV (256*PAD)
#define ATT_BUFTOT (ATT_KV + 64*MSTR*2)     // KV bf16 + mask fp32 region (bf16 units)
#define ATT_BUFTOTB (ATT_BUFTOT*2)
#define ATT_SMEM ((ATT_QBUF + 2*ATT_BUFTOT)*2)
__global__ __launch_bounds__(256) void attn_h(const float* __restrict__ mask){
    extern __shared__ __nv_bfloat16 sm[];
    const int t = threadIdx.x, lane = t & 31, w = t >> 5;
    const int wn = w & 3, wm = w >> 2;      // 4(n) x 2(m); warp 32n x 32m
    const int n0 = blockIdx.x*128, k = blockIdx.y, b = blockIdx.z;
    const size_t bk = (size_t)(b*NH + k);
    const u32 sm0 = sptr(sm);

    // Q tiles once (async, first group)
    {
        const int qr = t >> 1, qc8 = (t & 1)*32;   // 128 rows, two 32-elem halves... (use 16B ops)
        // simpler: original loop, runs once
        for (int i = t; i < 2048; i += 256){
            int arr = i >> 10, idx = i & 1023, r = idx >> 3, c8 = (idx & 7)*8;
            const __nv_bfloat16* src = (arr ? g_Qpl : g_Qph) + (bk*NTOK + n0 + r)*DH + c8;
            CPA(sm0 + (u32)(((arr ? 128*PAD : 0) + r*PAD + c8)*2), src);
        }
        (void)qr; (void)qc8;
    }

    // hoisted KV + mask cp.async addressing
    const int kr = t >> 3, kc8 = (t & 7)*8;     // rows 0..31
    const __nv_bfloat16* pK_h = g_Kph + (bk*NTOK + kr)*DH + kc8;
    const __nv_bfloat16* pK_l = g_Kpl + (bk*NTOK + kr)*DH + kc8;
    const __nv_bfloat16* pV_h = g_Vph + (bk*NTOK + kr)*DH + kc8;
    const __nv_bfloat16* pV_l = g_Vpl + (bk*NTOK + kr)*DH + kc8;
    const u32 dKV = sm0 + (u32)((ATT_QBUF + kr*PAD + kc8)*2);
    const float* pMsk = mask + (size_t)(t >> 5)*NTOK + n0 + (t & 31)*4;
    const u32 dM = sm0 + (u32)((ATT_QBUF + ATT_KV)*2) + (u32)(((t >> 5)*MSTR + (t & 31)*4)*4);
    int mkoff = 0;

    auto issueKV = [&](int pb){
        u32 db = dKV + (u32)(pb*ATT_BUFTOTB);
        CPA(db,               pK_h + mkoff);
        CPA(db + 32*PAD*2,    pK_h + mkoff + 32*DH);
        CPA(db + 64*PAD*2,    pK_l + mkoff);
        CPA(db + 96*PAD*2,    pK_l + mkoff + 32*DH);
        CPA(db + 128*PAD*2,   pV_h + mkoff);
        CPA(db + 160*PAD*2,   pV_h + mkoff + 32*DH);
        CPA(db + 192*PAD*2,   pV_l + mkoff);
        CPA(db + 224*PAD*2,   pV_l + mkoff + 32*DH);
        u32 dm = dM + (u32)(pb*ATT_BUFTOTB);
#pragma unroll
        for (int j = 0; j < 8; j++)
            CPA(dm + (u32)(j*8*MSTR*4), pMsk + (size_t)(8*j)*NTOK);
        CPC();
        mkoff += 64*DH;
        pMsk  += (size_t)64*NTOK;
    };

    float rsum[4];
#pragma unroll
    for (int j = 0; j < 4; j++) rsum[j] = 0.f;
    float Oacc[2][8][4];
#pragma unroll
    for (int i=0;i<2;i++)
#pragma unroll
    for (int j=0;j<8;j++)
#pragma unroll
    for (int e=0;e<4;e++) Oacc[i][j][e]=0.f;

    const int arow = lane & 15, acolh = (lane >> 4) << 3;
    const int brow = (lane & 7) + ((lane & 16) >> 1), bcolh = lane & 8;
    const int vrow = (lane & 7) + (lane & 8), vcolh = (lane & 16) >> 1;
    const u32 qBase = sm0 + (u32)(((wn*32 + arow)*PAD + acolh)*2);
    const u32 kBase = sm0 + (u32)((ATT_QBUF + (wm*32 + brow)*PAD + bcolh)*2);
    const u32 vBase = sm0 + (u32)((ATT_QBUF + 128*PAD + (wm*32 + vrow)*PAD + vcolh)*2);
    const int mi0 = (wm*32 + 2*(lane & 3))*MSTR + wn*32 + (lane >> 2);

    issueKV(0);
    for (int it = 0; it < NTOK/64; it++){
        CPW0(); __syncthreads();
        if (it + 1 < NTOK/64) issueKV((it + 1) & 1);
        const u32 bs = (u32)((it & 1)*ATT_BUFTOTB);
        const float* msk = (const float*)((const char*)sm +
            (size_t)((ATT_QBUF + ATT_KV)*2) + (it & 1)*ATT_BUFTOTB);

        float S[2][4][4];
#pragma unroll
        for (int i=0;i<2;i++)
#pragma unroll
        for (int j=0;j<4;j++)
#pragma unroll
        for (int e=0;e<4;e++) S[i][j][e]=0.f;
#pragma unroll
        for (int ks = 0; ks < 4; ks++){
            u32 qh[2][4], ql2[2][4], kh2[2][4], kl2[2][4];
#pragma unroll
            for (int nt = 0; nt < 2; nt++){
                ldsm4(qh[nt],  qBase + (u32)((nt*16*PAD + ks*16)*2));
                ldsm4(ql2[nt], qBase + (u32)(((128 + nt*16)*PAD + ks*16)*2));
            }
#pragma unroll
            for (int p = 0; p < 2; p++){
                ldsm4(kh2[p], kBase + bs + (u32)((p*16*PAD + ks*16)*2));
                ldsm4(kl2[p], kBase + bs + (u32)(((64 + p*16)*PAD + ks*16)*2));
            }
#pragma unroll
            for (int nt = 0; nt < 2; nt++)
#pragma unroll
            for (int p = 0; p < 2; p++){
                mma16816(S[nt][2*p],   qh[nt],  &kh2[p][0]);
                mma16816(S[nt][2*p+1], qh[nt],  &kh2[p][2]);
                mma16816(S[nt][2*p],   qh[nt],  &kl2[p][0]);
                mma16816(S[nt][2*p+1], qh[nt],  &kl2[p][2]);
                mma16816(S[nt][2*p],   ql2[nt], &kh2[p][0]);
                mma16816(S[nt][2*p+1], ql2[nt], &kh2[p][2]);
            }
        }
        // softmax (logits small; no max subtraction) + pack P fragments
        u32 ph[2][2][4], pl2[2][2][4];
#pragma unroll
        for (int nt = 0; nt < 2; nt++){
#pragma unroll
            for (int mt = 0; mt < 4; mt++)
#pragma unroll
            for (int e = 0; e < 4; e++){
                float mval = msk[mi0 + (mt*8 + (e & 1))*MSTR + nt*16 + (e >> 1)*8];
                float p = fexp2((S[nt][mt][e] + mval) * SM_SCALE);
                rsum[nt*2 + (e >> 1)] += p;
                S[nt][mt][e] = p;
            }
#pragma unroll
            for (int kp = 0; kp < 2; kp++){
                pack2(S[nt][2*kp][0],   S[nt][2*kp][1],   ph[nt][kp][0], pl2[nt][kp][0]);
                pack2(S[nt][2*kp][2],   S[nt][2*kp][3],   ph[nt][kp][1], pl2[nt][kp][1]);
                pack2(S[nt][2*kp+1][0], S[nt][2*kp+1][1], ph[nt][kp][2], pl2[nt][kp][2]);
                pack2(S[nt][2*kp+1][2], S[nt][2*kp+1][3], ph[nt][kp][3], pl2[nt][kp][3]);
            }
        }
        // O += P @ V
#pragma unroll
        for (int kp = 0; kp < 2; kp++){
            u32 vh2[4][4], vl2[4][4];
#pragma unroll
            for (int pd = 0; pd < 4; pd++){
                ldsm4t(vh2[pd], vBase + bs + (u32)((kp*16*PAD + pd*16)*2));
                ldsm4t(vl2[pd], vBase + bs + (u32)(((64 + kp*16)*PAD + pd*16)*2));
            }
#pragma unroll
            for (int nt = 0; nt < 2; nt++)
#pragma unroll
            for (int pd = 0; pd < 4; pd++){
                mma16816(Oacc[nt][2*pd],   ph[nt][kp],  &vh2[pd][0]);
                mma16816(Oacc[nt][2*pd+1], ph[nt][kp],  &vh2[pd][2]);
                mma16816(Oacc[nt][2*pd],   ph[nt][kp],  &vl2[pd][0]);
                mma16816(Oacc[nt][2*pd+1], ph[nt][kp],  &vl2[pd][2]);
                mma16816(Oacc[nt][2*pd],   pl2[nt][kp], &vh2[pd][0]);
                mma16816(Oacc[nt][2*pd+1], pl2[nt][kp], &vh2[pd][2]);
            }
        }
    }
    // epilogue: cross-warp (wm) reduce + rowsum normalize + split store
    __syncthreads();
    float* Osm  = (float*)sm;          // [128][65]
    float* rssm = Osm + 128*65;        // [128][8]
#pragma unroll
    for (int j = 0; j < 4; j++){
        int nl = wn*32 + (j >> 1)*16 + (lane >> 2) + (j & 1)*8;
        rssm[nl*8 + wm*4 + (lane & 3)] = rsum[j];
    }
    if (wm == 1){
#pragma unroll
        for (int nt = 0; nt < 2; nt++)
#pragma unroll
        for (int dt = 0; dt < 8; dt++)
#pragma unroll
        for (int e = 0; e < 4; e++){
            int nl = wn*32 + nt*16 + (lane >> 2) + (e >> 1)*8;
            int d  = dt*8 + 2*(lane & 3) + (e & 1);
            Osm[nl*65 + d] = Oacc[nt][dt][e];
        }
    }
    __syncthreads();
    if (wm == 0){
        float inv[4];
#pragma unroll
        for (int j = 0; j < 4; j++){
            int nl = wn*32 + (j >> 1)*16 + (lane >> 2) + (j & 1)*8;
            float s = 0.f;
#pragma unroll
            for (int q = 0; q < 8; q++) s += rssm[nl*8 + q];
            inv[j] = 1.0f / s;
        }
#pragma unroll
        for (int nt = 0; nt < 2; nt++)
#pragma unroll
        for (int dt = 0; dt < 8; dt++)
#pragma unroll
        for (int h = 0; h < 2; h++){
            int nl = wn*32 + nt*16 + (lane >> 2) + h*8;
            int d  = dt*8 + 2*(lane & 3);
            float iv = inv[nt*2 + h];
            float v0 = (Oacc[nt][dt][h*2]   + Osm[nl*65 + d])     * iv;
            float v1 = (Oacc[nt][dt][h*2+1] + Osm[nl*65 + d + 1]) * iv;
            u32 hi, lo; pack2(v0, v1, hi, lo);
            size_t off = ((size_t)(b*NTOK + n0 + nl))*KD + (size_t)k*DH + d;
            *(u32*)(g_Ohh + off) = hi;
            *(u32*)(g_Oll + off) = lo;
        }
    }
}

// ---------------- output GEMM: out[128 x 128] = O[128 x 1024] @ W2^T ---------
// 512 threads, 16 warps as 4(m) x 4(n); warp tile 32m x 32n
#define OUT_BUF (512*PAD)
#define OUT_BUFB (OUT_BUF*2)
#define OUT_SMEM (2*OUT_BUF*2)
__global__ __launch_bounds__(512) void out_h(float* __restrict__ out){
    extern __shared__ __nv_bfloat16 sm[];
    const int t = threadIdx.x, lane = t & 31, w = t >> 5;
    const int wm = w & 3, wn = w >> 2;
    const int q0 = blockIdx.x*128, r0 = blockIdx.y*128;
    const u32 sm0 = sptr(sm);

    const int ar = t >> 3, ac8 = (t & 7)*8;
    const __nv_bfloat16* pOh = g_Ohh + (size_t)(r0 + ar)*KD + ac8;
    const __nv_bfloat16* pOl = g_Oll + (size_t)(r0 + ar)*KD + ac8;
    const __nv_bfloat16* pBh = g_W2h + (size_t)(q0 + ar)*KD + ac8;
    const __nv_bfloat16* pBl = g_W2l + (size_t)(q0 + ar)*KD + ac8;
    const u32 dA = sm0 + (u32)((ar*PAD + ac8)*2);
    const u32 dB = sm0 + (u32)((256*PAD + ar*PAD + ac8)*2);
    int koff = 0;

    float acc[2][4][4];
#pragma unroll
    for (int i=0;i<2;i++)
#pragma unroll
    for (int j=0;j<4;j++)
#pragma unroll
    for (int e=0;e<4;e++) acc[i][j][e]=0.f;

    const int arow = lane & 15, acolh = (lane >> 4) << 3;
    const int brow = (lane & 7) + ((lane & 16) >> 1), bcolh = lane & 8;
    const u32 aBase = sm0 + (u32)(((wm*32 + arow)*PAD + acolh)*2);
    const u32 bBase = sm0 + (u32)((256*PAD + (wn*32 + brow)*PAD + bcolh)*2);

    auto issue = [&](int pb){
        u32 da = dA + (u32)(pb*OUT_BUFB);
        CPA(da,               pOh + koff);
        CPA(da + 64*PAD*2,    pOh + koff + 64*KD);
        CPA(da + 128*PAD*2,   pOl + koff);
        CPA(da + 192*PAD*2,   pOl + koff + 64*KD);
        u32 db = dB + (u32)(pb*OUT_BUFB);
        CPA(db,               pBh + koff);
        CPA(db + 64*PAD*2,    pBh + koff + 64*KD);
        CPA(db + 128*PAD*2,   pBl + koff);
        CPA(db + 192*PAD*2,   pBl + koff + 64*KD);
        CPC();
        koff += 64;
    };

    issue(0);
    for (int it = 0; it < 16; it++){
        CPW0(); __syncthreads();
        if (it + 1 < 16) issue((it + 1) & 1);
        const u32 bs = (u32)((it & 1)*OUT_BUFB);
#pragma unroll
        for (int ks = 0; ks < 4; ks++){
            u32 ah[2][4], al2[2][4], bh[2][4], bl2[2][4];
#pragma unroll
            for (int mt = 0; mt < 2; mt++){
                ldsm4(ah[mt],  aBase + bs + (u32)((mt*16*PAD + ks*16)*2));
                ldsm4(al2[mt], aBase + bs + (u32)(((128 + mt*16)*PAD + ks*16)*2));
            }
#pragma unroll
            for (int p = 0; p < 2; p++){
                ldsm4(bh[p],  bBase + bs + (u32)((p*16*PAD + ks*16)*2));
                ldsm4(bl2[p], bBase + bs + (u32)(((128 + p*16)*PAD + ks*16)*2));
            }
#pragma unroll
            for (int mt = 0; mt < 2; mt++)
#pragma unroll
            for (int p = 0; p < 2; p++){
                mma16816(acc[mt][2*p],   ah[mt],  &bh[p][0]);
                mma16816(acc[mt][2*p+1], ah[mt],  &bh[p][2]);
                mma16816(acc[mt][2*p],   ah[mt],  &bl2[p][0]);
                mma16816(acc[mt][2*p+1], ah[mt],  &bl2[p][2]);
                mma16816(acc[mt][2*p],   al2[mt], &bh[p][0]);
                mma16816(acc[mt][2*p+1], al2[mt], &bh[p][2]);
            }
        }
    }
#pragma unroll
    for (int mt = 0; mt < 2; mt++)
#pragma unroll
    for (int nt = 0; nt < 4; nt++)
#pragma unroll
    for (int h = 0; h < 2; h++){
        int r = r0 + wm*32 + mt*16 + (lane >> 2) + h*8;
        int c = q0 + wn*32 + nt*8 + 2*(lane & 3);
        *(float2*)(out + (size_t)r*CDIM + c) =
            make_float2(acc[mt][nt][h*2], acc[mt][nt][h*2+1]);
    }
}

// -----------------------------------------------------------------------------
extern "C" void kernel_launch(void* const* d_in, const int* in_sizes, int n_in,
                              void* d_out, int out_size)
{
    (void)in_sizes; (void)n_in; (void)out_size;
    const float* y    = (const float*)d_in[0];
    const float* mask = (const float*)d_in[1];
    const float* Lx   = (const float*)d_in[2];
    const float* Ly   = (const float*)d_in[3];
    const float* Tx   = (const float*)d_in[4];
    const float* Ty   = (const float*)d_in[5];
    float* out = (float*)d_out;

    cudaFuncSetAttribute(proj_h, cudaFuncAttributeMaxDynamicSharedMemorySize, PROJ_SMEM);
    cudaFuncSetAttribute(attn_h, cudaFuncAttributeMaxDynamicSharedMemorySize, ATT_SMEM);
    cudaFuncSetAttribute(out_h,  cudaFuncAttributeMaxDynamicSharedMemorySize, OUT_SMEM);

    split_y_k<<<4096, 256>>>(y);
    wcat_k<<<dim3(32, 2, 48), dim3(32, 8)>>>(Lx, Ly, Tx);
    wout_k<<<1024, 256>>>(Ty);
    proj_h<<<dim3(NTOK/128, NH, BB), 512, PROJ_SMEM>>>();
    attn_h<<<dim3(NTOK/128, NH, BB), 256, ATT_SMEM>>>(mask);
    out_h<<<dim3(CDIM/128, (BB*NTOK)/128), 512, OUT_SMEM>>>(out);
}

// round 10
// speedup vs baseline: 4.4385x; 1.4797x over previous
#include <cuda_runtime.h>
#include <cuda_fp16.h>

typedef unsigned int u32; typedef unsigned short u16; typedef unsigned long long u64;

#define BB 2
#define NTOK 2048
#define CDIM 1024
#define NH 16
#define DH 64
#define KD 1024
#define SM_SCALE 0.18033688011112042f  // log2(e)/sqrt(64)
#define SM_OFF 8.0f                    // uniform log2-domain offset; cancels in normalization
#define SM_CLAMP 15.5f                 // fp16 overflow insurance
#define PAD 72
#define MSTR 132

// scratch (static device arrays), all fp16
__device__ __half g_Yh[(size_t)BB*NTOK*CDIM];
__device__ __half g_Yl[(size_t)BB*NTOK*CDIM];
__device__ __half g_Wc[(size_t)NH*192*CDIM];    // [k][w*64+d][c] single fp16
__device__ __half g_Kp[(size_t)BB*NH*NTOK*DH];  // [bk][m][d] single
__device__ __half g_Qph[(size_t)BB*NH*NTOK*DH]; // split
__device__ __half g_Qpl[(size_t)BB*NH*NTOK*DH];
__device__ __half g_Vp[(size_t)BB*NH*NTOK*DH];  // single
__device__ __half g_Oh[(size_t)BB*NTOK*KD];     // [bn][k*64+d] split
__device__ __half g_Ol[(size_t)BB*NTOK*KD];
__device__ __half g_W2[(size_t)CDIM*KD];        // [q][k*64+d] single

// ---------------- helpers ----------------------------------------------------
__device__ __forceinline__ u32 sptr(const void* p){
    u32 a; asm("{ .reg .u64 t; cvta.to.shared.u64 t, %1; cvt.u32.u64 %0, t; }" : "=r"(a) : "l"(p)); return a;
}
#define CPA(dst, src) asm volatile("cp.async.cg.shared.global [%0], [%1], 16;" :: "r"(dst), "l"(src))
#define CPC()  asm volatile("cp.async.commit_group;" ::: "memory")
#define CPW0() asm volatile("cp.async.wait_group 0;" ::: "memory")

__device__ __forceinline__ void splith(float v, u16& h, u16& l){
    __half hb = __float2half_rn(v);
    __half lb = __float2half_rn(v - __half2float(hb));
    h = __half_as_ushort(hb); l = __half_as_ushort(lb);
}
__device__ __forceinline__ void pack2h(float x, float y, u32& hi, u32& lo){
    u16 hx,lx,hy,ly; splith(x,hx,lx); splith(y,hy,ly);
    hi = (u32)hx | ((u32)hy << 16); lo = (u32)lx | ((u32)ly << 16);
}
__device__ __forceinline__ u32 pack2s(float x, float y){
    return (u32)__half_as_ushort(__float2half_rn(x)) |
           ((u32)__half_as_ushort(__float2half_rn(y)) << 16);
}
__device__ __forceinline__ float fexp2(float x){
    float y; asm("ex2.approx.ftz.f32 %0, %1;" : "=f"(y) : "f"(x)); return y;
}
__device__ __forceinline__ void mma16816(float* c, const u32* a, const u32* b){
    asm volatile("mma.sync.aligned.m16n8k16.row.col.f32.f16.f16.f32 "
        "{%0,%1,%2,%3}, {%4,%5,%6,%7}, {%8,%9}, {%0,%1,%2,%3};"
        : "+f"(c[0]), "+f"(c[1]), "+f"(c[2]), "+f"(c[3])
        : "r"(a[0]), "r"(a[1]), "r"(a[2]), "r"(a[3]), "r"(b[0]), "r"(b[1]));
}
__device__ __forceinline__ void ldsm4(u32* r, u32 a){
    asm volatile("ldmatrix.sync.aligned.m8n8.x4.shared.b16 {%0,%1,%2,%3}, [%4];"
        : "=r"(r[0]), "=r"(r[1]), "=r"(r[2]), "=r"(r[3]) : "r"(a));
}
__device__ __forceinline__ void ldsm4t(u32* r, u32 a){
    asm volatile("ldmatrix.sync.aligned.m8n8.x4.trans.shared.b16 {%0,%1,%2,%3}, [%4];"
        : "=r"(r[0]), "=r"(r[1]), "=r"(r[2]), "=r"(r[3]) : "r"(a));
}

// ---------------- prep kernels ------------------------------------------------
__global__ __launch_bounds__(256) void split_y_k(const float* __restrict__ y){
    size_t i = ((size_t)blockIdx.x*256 + threadIdx.x) * 4;
    float4 v = *(const float4*)(y + i);
    u32 h01,l01,h23,l23;
    pack2h(v.x, v.y, h01, l01); pack2h(v.z, v.w, h23, l23);
    *(uint2*)(g_Yh + i) = make_uint2(h01, h23);
    *(uint2*)(g_Yl + i) = make_uint2(l01, l23);
}
__global__ __launch_bounds__(256) void wcat_k(const float* __restrict__ Lx,
        const float* __restrict__ Ly, const float* __restrict__ Tx){
    __shared__ float t[32][33];
    int k = blockIdx.z / 3, w = blockIdx.z % 3;
    const float* src = (w == 0) ? Lx : ((w == 1) ? Ly : Tx);
    int c0 = blockIdx.x * 32, d0 = blockIdx.y * 32;
    int tx = threadIdx.x, ty = threadIdx.y;
#pragma unroll
    for (int s = 0; s < 4; s++)
        t[ty + 8*s][tx] = src[((size_t)k*CDIM + c0 + ty + 8*s)*DH + d0 + tx];
    __syncthreads();
#pragma unroll
    for (int s = 0; s < 4; s++){
        int r = ty + 8*s;
        size_t o = ((size_t)k*192 + w*64 + d0 + r)*CDIM + c0 + tx;
        g_Wc[o] = __float2half_rn(t[tx][r]);
    }
}
__global__ __launch_bounds__(256) void wout_k(const float* __restrict__ Ty){
    size_t i = ((size_t)blockIdx.x*256 + threadIdx.x) * 4;
    int k = (int)(i >> 16), q = (int)((i >> 6) & 1023), d = (int)(i & 63);
    float4 v = *(const float4*)(Ty + i);
    size_t o = (size_t)q*KD + (size_t)k*64 + d;
    *(uint2*)(g_W2 + o) = make_uint2(pack2s(v.x, v.y), pack2s(v.z, v.w));
}

// ---------------- projection: D[128 x 192] = Y[128 x 1024] @ Wc^T ------------
// 512 threads, 16 warps as 4(m) x 4(n); warp tile 32m x 48n
#define PROJ_BUF (448*PAD)
#define PROJ_BUFB (PROJ_BUF*2)
#define PROJ_SMEM (2*PROJ_BUF*2)
__global__ __launch_bounds__(512) void proj_h(){
    extern __shared__ __half sm[];
    const int t = threadIdx.x, lane = t & 31, w = t >> 5;
    const int wm = w & 3, wn = w >> 2;
    const int m0 = blockIdx.x*128, k = blockIdx.y, b = blockIdx.z;
    const size_t bk = (size_t)(b*NH + k);
    const u32 sm0 = sptr(sm);

    const int ar = t >> 3, ac8 = (t & 7)*8;   // 64 rows per CPA round
    const __half* pYh = g_Yh + (size_t)(b*NTOK + m0 + ar)*CDIM + ac8;
    const __half* pYl = g_Yl + (size_t)(b*NTOK + m0 + ar)*CDIM + ac8;
    const __half* pW  = g_Wc + ((size_t)k*192 + ar)*CDIM + ac8;
    const u32 dA = sm0 + (u32)((ar*PAD + ac8)*2);
    const u32 dB = sm0 + (u32)((256*PAD + ar*PAD + ac8)*2);
    int koff = 0;

    float acc[2][6][4];
#pragma unroll
    for (int i=0;i<2;i++)
#pragma unroll
    for (int j=0;j<6;j++)
#pragma unroll
    for (int e=0;e<4;e++) acc[i][j][e]=0.f;

    const int arow = lane & 15, acolh = (lane >> 4) << 3;
    const int brow = (lane & 7) + ((lane & 16) >> 1), bcolh = lane & 8;
    const u32 aBase = sm0 + (u32)(((wm*32 + arow)*PAD + acolh)*2);
    const u32 bBase = sm0 + (u32)((256*PAD + (wn*48 + brow)*PAD + bcolh)*2);

    auto issue = [&](int pb){
        u32 da = dA + (u32)(pb*PROJ_BUFB);
        CPA(da,             pYh + koff);
        CPA(da + 64*PAD*2,  pYh + koff + 64*CDIM);
        CPA(da + 128*PAD*2, pYl + koff);
        CPA(da + 192*PAD*2, pYl + koff + 64*CDIM);
        u32 db = dB + (u32)(pb*PROJ_BUFB);
        CPA(db,             pW + koff);
        CPA(db + 64*PAD*2,  pW + koff + 64*CDIM);
        CPA(db + 128*PAD*2, pW + koff + 128*CDIM);
        CPC();
        koff += 64;
    };

    issue(0);
    for (int it = 0; it < 16; it++){
        CPW0(); __syncthreads();
        if (it + 1 < 16) issue((it + 1) & 1);
        const u32 bs = (u32)((it & 1)*PROJ_BUFB);
#pragma unroll
        for (int ks = 0; ks < 4; ks++){
            u32 ah[2][4], al2[2][4], bh[3][4];
#pragma unroll
            for (int mt = 0; mt < 2; mt++){
                ldsm4(ah[mt],  aBase + bs + (u32)((mt*16*PAD + ks*16)*2));
                ldsm4(al2[mt], aBase + bs + (u32)(((128 + mt*16)*PAD + ks*16)*2));
            }
#pragma unroll
            for (int p = 0; p < 3; p++)
                ldsm4(bh[p], bBase + bs + (u32)((p*16*PAD + ks*16)*2));
#pragma unroll
            for (int mt = 0; mt < 2; mt++)
#pragma unroll
            for (int p = 0; p < 3; p++){
                mma16816(acc[mt][2*p],   ah[mt],  &bh[p][0]);
                mma16816(acc[mt][2*p+1], ah[mt],  &bh[p][2]);
                mma16816(acc[mt][2*p],   al2[mt], &bh[p][0]);
                mma16816(acc[mt][2*p+1], al2[mt], &bh[p][2]);
            }
        }
    }
    // epilogue: K single, Q split, V single (token-major [m][64])
#pragma unroll
    for (int mt = 0; mt < 2; mt++)
#pragma unroll
    for (int nt = 0; nt < 6; nt++){
        int cbase = wn*48 + nt*8 + 2*(lane & 3);
        int wsel = cbase >> 6, d = cbase & 63;
#pragma unroll
        for (int h = 0; h < 2; h++){
            int m = m0 + wm*32 + mt*16 + (lane >> 2) + h*8;
            size_t off = (bk*NTOK + m)*DH + d;
            float v0 = acc[mt][nt][h*2], v1 = acc[mt][nt][h*2+1];
            if (wsel == 1){
                u32 hi, lo; pack2h(v0, v1, hi, lo);
                *(u32*)(g_Qph + off) = hi;
                *(u32*)(g_Qpl + off) = lo;
            } else {
                __half* dst = (wsel == 0) ? g_Kp : g_Vp;
                *(u32*)(dst + off) = pack2s(v0, v1);
            }
        }
    }
}

// ---------------- attention: 128 queries/CTA, 64-key chunks ------------------
#define ATT_QBUF (256*PAD)
#define ATT_KV (128*PAD)
#define ATT_BUFTOT (ATT_KV + 64*MSTR*2)     // KV fp16 + mask fp32 (half units)
#define ATT_BUFTOTB (ATT_BUFTOT*2)
#define ATT_SMEM ((ATT_QBUF + 2*ATT_BUFTOT)*2)
__global__ __launch_bounds__(256) void attn_h(const float* __restrict__ mask){
    extern __shared__ __half sm[];
    const int t = threadIdx.x, lane = t & 31, w = t >> 5;
    const int wn = w & 3, wm = w >> 2;      // 4(n) x 2(m); warp 32n x 32m
    const int n0 = blockIdx.x*128, k = blockIdx.y, b = blockIdx.z;
    const size_t bk = (size_t)(b*NH + k);
    const u32 sm0 = sptr(sm);

    // Q tiles once (hi at 0, lo at 128*PAD)
    for (int i = t; i < 2048; i += 256){
        int arr = i >> 10, idx = i & 1023, r = idx >> 3, c8 = (idx & 7)*8;
        const __half* src = (arr ? g_Qpl : g_Qph) + (bk*NTOK + n0 + r)*DH + c8;
        CPA(sm0 + (u32)(((arr ? 128*PAD : 0) + r*PAD + c8)*2), src);
    }

    // hoisted KV + mask cp.async addressing
    const int kr = t >> 3, kc8 = (t & 7)*8;     // rows 0..31
    const __half* pK = g_Kp + (bk*NTOK + kr)*DH + kc8;
    const __half* pV = g_Vp + (bk*NTOK + kr)*DH + kc8;
    const u32 dKV = sm0 + (u32)((ATT_QBUF + kr*PAD + kc8)*2);
    const float* pMsk = mask + (size_t)(t >> 5)*NTOK + n0 + (t & 31)*4;
    const u32 dM = sm0 + (u32)((ATT_QBUF + ATT_KV)*2) + (u32)(((t >> 5)*MSTR + (t & 31)*4)*4);
    int mkoff = 0;

    auto issueKV = [&](int pb){
        u32 db = dKV + (u32)(pb*ATT_BUFTOTB);
        CPA(db,             pK + mkoff);
        CPA(db + 32*PAD*2,  pK + mkoff + 32*DH);
        CPA(db + 64*PAD*2,  pV + mkoff);
        CPA(db + 96*PAD*2,  pV + mkoff + 32*DH);
        u32 dm = dM + (u32)(pb*ATT_BUFTOTB);
#pragma unroll
        for (int j = 0; j < 8; j++)
            CPA(dm + (u32)(j*8*MSTR*4), pMsk + (size_t)(8*j)*NTOK);
        CPC();
        mkoff += 64*DH;
        pMsk  += (size_t)64*NTOK;
    };

    float rsum[4];
#pragma unroll
    for (int j = 0; j < 4; j++) rsum[j] = 0.f;
    float Oacc[2][8][4];
#pragma unroll
    for (int i=0;i<2;i++)
#pragma unroll
    for (int j=0;j<8;j++)
#pragma unroll
    for (int e=0;e<4;e++) Oacc[i][j][e]=0.f;

    const int arow = lane & 15, acolh = (lane >> 4) << 3;
    const int brow = (lane & 7) + ((lane & 16) >> 1), bcolh = lane & 8;
    const int vrow = (lane & 7) + (lane & 8), vcolh = (lane & 16) >> 1;
    const u32 qBase = sm0 + (u32)(((wn*32 + arow)*PAD + acolh)*2);
    const u32 kBase = sm0 + (u32)((ATT_QBUF + (wm*32 + brow)*PAD + bcolh)*2);
    const u32 vBase = sm0 + (u32)((ATT_QBUF + 64*PAD + (wm*32 + vrow)*PAD + vcolh)*2);
    const int mi0 = (wm*32 + 2*(lane & 3))*MSTR + wn*32 + (lane >> 2);

    issueKV(0);
    for (int it = 0; it < NTOK/64; it++){
        CPW0(); __syncthreads();
        if (it + 1 < NTOK/64) issueKV((it + 1) & 1);
        const u32 bs = (u32)((it & 1)*ATT_BUFTOTB);
        const float* msk = (const float*)((const char*)sm +
            (size_t)((ATT_QBUF + ATT_KV)*2) + (it & 1)*ATT_BUFTOTB);

        float S[2][4][4];
#pragma unroll
        for (int i=0;i<2;i++)
#pragma unroll
        for (int j=0;j<4;j++)
#pragma unroll
        for (int e=0;e<4;e++) S[i][j][e]=0.f;
#pragma unroll
        for (int ks = 0; ks < 4; ks++){
            u32 qh[2][4], ql2[2][4], kh2[2][4];
#pragma unroll
            for (int nt = 0; nt < 2; nt++){
                ldsm4(qh[nt],  qBase + (u32)((nt*16*PAD + ks*16)*2));
                ldsm4(ql2[nt], qBase + (u32)(((128 + nt*16)*PAD + ks*16)*2));
            }
#pragma unroll
            for (int p = 0; p < 2; p++)
                ldsm4(kh2[p], kBase + bs + (u32)((p*16*PAD + ks*16)*2));
#pragma unroll
            for (int nt = 0; nt < 2; nt++)
#pragma unroll
            for (int p = 0; p < 2; p++){
                mma16816(S[nt][2*p],   qh[nt],  &kh2[p][0]);
                mma16816(S[nt][2*p+1], qh[nt],  &kh2[p][2]);
                mma16816(S[nt][2*p],   ql2[nt], &kh2[p][0]);
                mma16816(S[nt][2*p+1], ql2[nt], &kh2[p][2]);
            }
        }
        // softmax: uniform log2-domain offset (cancels in normalization) + clamp
        u32 ph[2][2][4], pl2[2][2][4];
#pragma unroll
        for (int nt = 0; nt < 2; nt++){
#pragma unroll
            for (int mt = 0; mt < 4; mt++)
#pragma unroll
            for (int e = 0; e < 4; e++){
                float mval = msk[mi0 + (mt*8 + (e & 1))*MSTR + nt*16 + (e >> 1)*8];
                float x = (S[nt][mt][e] + mval) * SM_SCALE - SM_OFF;
                float p = fexp2(fminf(x, SM_CLAMP));
                rsum[nt*2 + (e >> 1)] += p;
                S[nt][mt][e] = p;
            }
#pragma unroll
            for (int kp = 0; kp < 2; kp++){
                pack2h(S[nt][2*kp][0],   S[nt][2*kp][1],   ph[nt][kp][0], pl2[nt][kp][0]);
                pack2h(S[nt][2*kp][2],   S[nt][2*kp][3],   ph[nt][kp][1], pl2[nt][kp][1]);
                pack2h(S[nt][2*kp+1][0], S[nt][2*kp+1][1], ph[nt][kp][2], pl2[nt][kp][2]);
                pack2h(S[nt][2*kp+1][2], S[nt][2*kp+1][3], ph[nt][kp][3], pl2[nt][kp][3]);
            }
        }
        // O += P @ V  (P split, V single)
#pragma unroll
        for (int kp = 0; kp < 2; kp++){
            u32 vh2[4][4];
#pragma unroll
            for (int pd = 0; pd < 4; pd++)
                ldsm4t(vh2[pd], vBase + bs + (u32)((kp*16*PAD + pd*16)*2));
#pragma unroll
            for (int nt = 0; nt < 2; nt++)
#pragma unroll
            for (int pd = 0; pd < 4; pd++){
                mma16816(Oacc[nt][2*pd],   ph[nt][kp],  &vh2[pd][0]);
                mma16816(Oacc[nt][2*pd+1], ph[nt][kp],  &vh2[pd][2]);
                mma16816(Oacc[nt][2*pd],   pl2[nt][kp], &vh2[pd][0]);
                mma16816(Oacc[nt][2*pd+1], pl2[nt][kp], &vh2[pd][2]);
            }
        }
    }
    // epilogue: cross-warp (wm) reduce + rowsum normalize + split store
    __syncthreads();
    float* Osm  = (float*)sm;          // [128][65]
    float* rssm = Osm + 128*65;        // [128][8]
#pragma unroll
    for (int j = 0; j < 4; j++){
        int nl = wn*32 + (j >> 1)*16 + (lane >> 2) + (j & 1)*8;
        rssm[nl*8 + wm*4 + (lane & 3)] = rsum[j];
    }
    if (wm == 1){
#pragma unroll
        for (int nt = 0; nt < 2; nt++)
#pragma unroll
        for (int dt = 0; dt < 8; dt++)
#pragma unroll
        for (int e = 0; e < 4; e++){
            int nl = wn*32 + nt*16 + (lane >> 2) + (e >> 1)*8;
            int d  = dt*8 + 2*(lane & 3) + (e & 1);
            Osm[nl*65 + d] = Oacc[nt][dt][e];
        }
    }
    __syncthreads();
    if (wm == 0){
        float inv[4];
#pragma unroll
        for (int j = 0; j < 4; j++){
            int nl = wn*32 + (j >> 1)*16 + (lane >> 2) + (j & 1)*8;
            float s = 0.f;
#pragma unroll
            for (int q = 0; q < 8; q++) s += rssm[nl*8 + q];
            inv[j] = 1.0f / s;
        }
#pragma unroll
        for (int nt = 0; nt < 2; nt++)
#pragma unroll
        for (int dt = 0; dt < 8; dt++)
#pragma unroll
        for (int h = 0; h < 2; h++){
            int nl = wn*32 + nt*16 + (lane >> 2) + h*8;
            int d  = dt*8 + 2*(lane & 3);
            float iv = inv[nt*2 + h];
            float v0 = (Oacc[nt][dt][h*2]   + Osm[nl*65 + d])     * iv;
            float v1 = (Oacc[nt][dt][h*2+1] + Osm[nl*65 + d + 1]) * iv;
            u32 hi, lo; pack2h(v0, v1, hi, lo);
            size_t off = ((size_t)(b*NTOK + n0 + nl))*KD + (size_t)k*DH + d;
            *(u32*)(g_Oh + off) = hi;
            *(u32*)(g_Ol + off) = lo;
        }
    }
}

// ---------------- output GEMM: out[128 x 128] = O[128 x 1024] @ W2^T ---------
// 512 threads, 16 warps as 4(m) x 4(n); warp tile 32m x 32n
#define OUT_BUF (384*PAD)
#define OUT_BUFB (OUT_BUF*2)
#define OUT_SMEM (2*OUT_BUF*2)
__global__ __launch_bounds__(512) void out_h(float* __restrict__ out){
    extern __shared__ __half sm[];
    const int t = threadIdx.x, lane = t & 31, w = t >> 5;
    const int wm = w & 3, wn = w >> 2;
    const int q0 = blockIdx.x*128, r0 = blockIdx.y*128;
    const u32 sm0 = sptr(sm);

    const int ar = t >> 3, ac8 = (t & 7)*8;
    const __half* pOh = g_Oh + (size_t)(r0 + ar)*KD + ac8;
    const __half* pOl = g_Ol + (size_t)(r0 + ar)*KD + ac8;
    const __half* pB  = g_W2 + (size_t)(q0 + ar)*KD + ac8;
    const u32 dA = sm0 + (u32)((ar*PAD + ac8)*2);
    const u32 dB = sm0 + (u32)((256*PAD + ar*PAD + ac8)*2);
    int koff = 0;

    float acc[2][4][4];
#pragma unroll
    for (int i=0;i<2;i++)
#pragma unroll
    for (int j=0;j<4;j++)
#pragma unroll
    for (int e=0;e<4;e++) acc[i][j][e]=0.f;

    const int arow = lane & 15, acolh = (lane >> 4) << 3;
    const int brow = (lane & 7) + ((lane & 16) >> 1), bcolh = lane & 8;
    const u32 aBase = sm0 + (u32)(((wm*32 + arow)*PAD + acolh)*2);
    const u32 bBase = sm0 + (u32)((256*PAD + (wn*32 + brow)*PAD + bcolh)*2);

    auto issue = [&](int pb){
        u32 da = dA + (u32)(pb*OUT_BUFB);
        CPA(da,             pOh + koff);
        CPA(da + 64*PAD*2,  pOh + koff + 64*KD);
        CPA(da + 128*PAD*2, pOl + koff);
        CPA(da + 192*PAD*2, pOl + koff + 64*KD);
        u32 db = dB + (u32)(pb*OUT_BUFB);
        CPA(db,             pB + koff);
        CPA(db + 64*PAD*2,  pB + koff + 64*KD);
        CPC();
        koff += 64;
    };

    issue(0);
    for (int it = 0; it < 16; it++){
        CPW0(); __syncthreads();
        if (it + 1 < 16) issue((it + 1) & 1);
        const u32 bs = (u32)((it & 1)*OUT_BUFB);
#pragma unroll
        for (int ks = 0; ks < 4; ks++){
            u32 ah[2][4], al2[2][4], bh[2][4];
#pragma unroll
            for (int mt = 0; mt < 2; mt++){
                ldsm4(ah[mt],  aBase + bs + (u32)((mt*16*PAD + ks*16)*2));
                ldsm4(al2[mt], aBase + bs + (u32)(((128 + mt*16)*PAD + ks*16)*2));
            }
#pragma unroll
            for (int p = 0; p < 2; p++)
                ldsm4(bh[p], bBase + bs + (u32)((p*16*PAD + ks*16)*2));
#pragma unroll
            for (int mt = 0; mt < 2; mt++)
#pragma unroll
            for (int p = 0; p < 2; p++){
                mma16816(acc[mt][2*p],   ah[mt],  &bh[p][0]);
                mma16816(acc[mt][2*p+1], ah[mt],  &bh[p][2]);
                mma16816(acc[mt][2*p],   al2[mt], &bh[p][0]);
                mma16816(acc[mt][2*p+1], al2[mt], &bh[p][2]);
            }
        }
    }
#pragma unroll
    for (int mt = 0; mt < 2; mt++)
#pragma unroll
    for (int nt = 0; nt < 4; nt++)
#pragma unroll
    for (int h = 0; h < 2; h++){
        int r = r0 + wm*32 + mt*16 + (lane >> 2) + h*8;
        int c = q0 + wn*32 + nt*8 + 2*(lane & 3);
        *(float2*)(out + (size_t)r*CDIM + c) =
            make_float2(acc[mt][nt][h*2], acc[mt][nt][h*2+1]);
    }
}

// -----------------------------------------------------------------------------
extern "C" void kernel_launch(void* const* d_in, const int* in_sizes, int n_in,
                              void* d_out, int out_size)
{
    (void)in_sizes; (void)n_in; (void)out_size;
    const float* y    = (const float*)d_in[0];
    const float* mask = (const float*)d_in[1];
    const float* Lx   = (const float*)d_in[2];
    const float* Ly   = (const float*)d_in[3];
    const float* Tx   = (const float*)d_in[4];
    const float* Ty   = (const float*)d_in[5];
    float* out = (float*)d_out;

    cudaFuncSetAttribute(proj_h, cudaFuncAttributeMaxDynamicSharedMemorySize, PROJ_SMEM);
    cudaFuncSetAttribute(attn_h, cudaFuncAttributeMaxDynamicSharedMemorySize, ATT_SMEM);
    cudaFuncSetAttribute(out_h,  cudaFuncAttributeMaxDynamicSharedMemorySize, OUT_SMEM);

    split_y_k<<<4096, 256>>>(y);
    wcat_k<<<dim3(32, 2, 48), dim3(32, 8)>>>(Lx, Ly, Tx);
    wout_k<<<1024, 256>>>(Ty);
    proj_h<<<dim3(NTOK/128, NH, BB), 512, PROJ_SMEM>>>();
    attn_h<<<dim3(NTOK/128, NH, BB), 256, ATT_SMEM>>>(mask);
    out_h<<<dim3(CDIM/128, (BB*NTOK)/128), 512, OUT_SMEM>>>(out);
}